// round 15
// baseline (speedup 1.0000x reference)
#include <cuda_runtime.h>
#include <cuda_bf16.h>
#include <math.h>
#include <stdint.h>

#define HID 128
#define MAX_N 100352
#define MAXSTEPS 8
#define NG 256
#define MAX_E 2000000

// ---------------- scratch (static device globals; no runtime allocation) ----
__device__ __align__(16) uint32_t g_hHa [MAX_N * 64];      // ping-pong h splits
__device__ __align__(16) uint32_t g_hLa [MAX_N * 64];
__device__ __align__(16) uint32_t g_hHb [MAX_N * 64];
__device__ __align__(16) uint32_t g_hLb [MAX_N * 64];
__device__ __align__(16) uint32_t g_hsH [MAX_N * 64];      // hsum split
__device__ __align__(16) uint32_t g_hsL [MAX_N * 64];
__device__ __align__(16) uint32_t g_xH  [MAX_N * 48];
__device__ __align__(16) uint32_t g_xL  [MAX_N * 48];
__device__ __align__(16) float    g_Wfold[MAXSTEPS * 128 * 384];   // W_mpnn[s] @ w_ih^T
__device__ __align__(16) uint32_t g_BgTH[MAXSTEPS * 512 * 128];    // permuted B'' split
__device__ __align__(16) uint32_t g_BgTL[MAXSTEPS * 512 * 128];
__device__ __align__(16) uint32_t g_WembTH[128 * 48];
__device__ __align__(16) uint32_t g_WembTL[128 * 48];
__device__ __align__(16) float    g_bcat[512];             // permuted bias
__device__ int g_deg[MAX_N];
__device__ int g_rowptr[MAX_N + 1];
__device__ int g_cursor[MAX_N];
__device__ int g_esrc[MAX_E];
__device__ int g_starts[NG + 1];

// ---------------- helpers ----------------------------------------------------
__device__ __forceinline__ void split2(float x, float y, uint32_t& hi, uint32_t& lo) {
    __nv_bfloat16 hx = __float2bfloat16_rn(x);
    __nv_bfloat16 hy = __float2bfloat16_rn(y);
    float rx = x - __bfloat162float(hx);
    float ry = y - __bfloat162float(hy);
    __nv_bfloat162 h; h.x = hx; h.y = hy;
    __nv_bfloat162 l; l.x = __float2bfloat16_rn(rx); l.y = __float2bfloat16_rn(ry);
    hi = *(uint32_t*)&h;
    lo = *(uint32_t*)&l;
}

__device__ __forceinline__ void unsplit2(uint32_t hi, uint32_t lo, float& x, float& y) {
    __nv_bfloat162 h = *(__nv_bfloat162*)&hi;
    __nv_bfloat162 l = *(__nv_bfloat162*)&lo;
    x = __bfloat162float(h.x) + __bfloat162float(l.x);
    y = __bfloat162float(h.y) + __bfloat162float(l.y);
}

__device__ __forceinline__ void mma_bf16(float* c, const uint32_t* a, const uint32_t* b) {
    asm volatile(
        "mma.sync.aligned.m16n8k16.row.col.f32.bf16.bf16.f32 "
        "{%0,%1,%2,%3}, {%4,%5,%6,%7}, {%8,%9}, {%0,%1,%2,%3};\n"
        : "+f"(c[0]), "+f"(c[1]), "+f"(c[2]), "+f"(c[3])
        : "r"(a[0]), "r"(a[1]), "r"(a[2]), "r"(a[3]),
          "r"(b[0]), "r"(b[1]));
}

__device__ __forceinline__ void ldsm4(uint32_t& r0, uint32_t& r1,
                                      uint32_t& r2, uint32_t& r3, uint32_t addr) {
    asm volatile("ldmatrix.sync.aligned.m8n8.x4.shared.b16 {%0,%1,%2,%3}, [%4];"
                 : "=r"(r0), "=r"(r1), "=r"(r2), "=r"(r3) : "r"(addr));
}

__device__ __forceinline__ float sigmoidf_(float x) {
    return 1.0f / (1.0f + expf(-x));
}

// permutation decode: group g = C>>3; m = g&3 -> comp {0:r,1:i,2:z,3:h};
// hidx = (g>>2)*8 + (C&7)
__device__ __forceinline__ int comp_of_m(int m) {
    return (m == 0) ? 0 : (m == 1) ? 2 : (m == 2) ? 1 : 3;
}

// ---------------- small utility kernels --------------------------------------
__global__ void zero_i(int* p, int n) {
    int i = blockIdx.x * blockDim.x + threadIdx.x;
    if (i < n) p[i] = 0;
}

// ---------------- weight fold / pack kernels ----------------------------------
// Wfold[s] = W_mpnn[s] @ w_ih^T   : [128 K][384 cols]
__global__ void fold_kernel(const float* __restrict__ Wm,
                            const float* __restrict__ wih,
                            float* __restrict__ Wfold, int steps) {
    int idx = blockIdx.x * blockDim.x + threadIdx.x;
    int total = steps * 128 * 384;
    if (idx >= total) return;
    int s = idx / (128 * 384);
    int rem = idx % (128 * 384);
    int k = rem / 384;
    int j = rem % 384;
    const float* wr = Wm + s * 128 * 128 + k * 128;
    const float* ir = wih + j * 128;
    float acc = 0.0f;
#pragma unroll 8
    for (int c = 0; c < 128; c++) acc = fmaf(wr[c], ir[c], acc);
    Wfold[idx] = acc;
}

// permuted B'' (period-32 col pattern r,i,z,h per 8-col group):
// C in [0,512): g=C>>3, m=g&3, comp = {0->r(0),1->i(2),2->z(1),3->h(3)},
// hidx = (g>>2)*8 + (C&7). K = [hsum kpairs 0..63 | h kpairs 64..127].
// r_sum,z_sum: full K; i_n: hsum half only; h_n: h half only.
__global__ void pack_BgT_kernel(const float* __restrict__ Wfold,
                                const float* __restrict__ whh,
                                uint32_t* __restrict__ WH, uint32_t* __restrict__ WL,
                                int steps) {
    int idx = blockIdx.x * blockDim.x + threadIdx.x;
    int total = steps * 512 * 128;
    if (idx >= total) return;
    int s = idx / (512 * 128);
    int rem = idx % (512 * 128);
    int C = rem / 128;
    int p = rem % 128;
    int g = C >> 3;
    int comp = comp_of_m(g & 3);
    int hidx = (g >> 2) * 8 + (C & 7);
    float a = 0.f, b = 0.f;
    if (p < 64) {                      // hsum half: Wfold cols (r=0,z=1,i_n=2)
        int k0 = 2 * p;
        if (comp < 3) {
            int j = comp * 128 + hidx;
            a = Wfold[s * 128 * 384 + k0 * 384 + j];
            b = Wfold[s * 128 * 384 + (k0 + 1) * 384 + j];
        }
    } else {                           // h half: w_hh rows (r, z, h_n)
        int k0 = 2 * (p - 64);
        int jj = -1;
        if (comp == 0)      jj = hidx;
        else if (comp == 1) jj = 128 + hidx;
        else if (comp == 3) jj = 256 + hidx;
        if (jj >= 0) { a = whh[jj * HID + k0]; b = whh[jj * HID + k0 + 1]; }
    }
    uint32_t h, l;
    split2(a, b, h, l);
    WH[idx] = h; WL[idx] = l;
}

__global__ void pack_bcat_kernel(const float* __restrict__ bih,
                                 const float* __restrict__ bhh,
                                 float* __restrict__ bcat) {
    int C = blockIdx.x * blockDim.x + threadIdx.x;
    if (C >= 512) return;
    int g = C >> 3;
    int comp = comp_of_m(g & 3);
    int hidx = (g >> 2) * 8 + (C & 7);
    float v;
    if (comp == 0)      v = bih[hidx] + bhh[hidx];
    else if (comp == 1) v = bih[128 + hidx] + bhh[128 + hidx];
    else if (comp == 2) v = bih[256 + hidx];
    else                v = bhh[256 + hidx];
    bcat[C] = v;
}

__global__ void pack_wembT_kernel(const float* __restrict__ We,
                                  uint32_t* __restrict__ WH, uint32_t* __restrict__ WL,
                                  int KPx) {
    int idx = blockIdx.x * blockDim.x + threadIdx.x;
    if (idx >= 128 * 48) return;
    int j = idx / 48;
    int p = idx % 48;
    uint32_t h = 0, l = 0;
    if (p < KPx) split2(We[(2 * p) * HID + j], We[(2 * p + 1) * HID + j], h, l);
    WH[idx] = h; WL[idx] = l;
}

__global__ void split_x_kernel(const float* __restrict__ x,
                               uint32_t* __restrict__ xH, uint32_t* __restrict__ xL,
                               int Nn, int F, int KPx, int Apx) {
    long long idx = (long long)blockIdx.x * blockDim.x + threadIdx.x;
    if (idx >= (long long)Nn * Apx) return;
    int n = (int)(idx / Apx);
    int p = (int)(idx % Apx);
    uint32_t h = 0, l = 0;
    if (p < KPx) split2(x[(long long)n * F + 2 * p], x[(long long)n * F + 2 * p + 1], h, l);
    xH[idx] = h; xL[idx] = l;
}

// ---------------- CSR build ---------------------------------------------------
__global__ void hist_kernel(const int* __restrict__ ei, long long E, int* __restrict__ deg) {
    long long e = (long long)blockIdx.x * blockDim.x + threadIdx.x;
    if (e >= E) return;
    atomicAdd(&deg[ei[E + e]], 1);
}

__global__ void scan_kernel(const int* __restrict__ deg, int* __restrict__ rowptr,
                            int* __restrict__ cursor, int Nn) {
    __shared__ int warpsums[32];
    const int tid = threadIdx.x;
    const int lane = tid & 31;
    const int wid = tid >> 5;
    int carry = 0;
    for (int base = 0; base < Nn; base += 1024) {
        int idx = base + tid;
        int v = (idx < Nn) ? deg[idx] : 0;
        int x = v;
#pragma unroll
        for (int off = 1; off < 32; off <<= 1) {
            int y = __shfl_up_sync(0xffffffffu, x, off);
            if (lane >= off) x += y;
        }
        if (lane == 31) warpsums[wid] = x;
        __syncthreads();
        if (wid == 0) {
            int z = warpsums[lane];
#pragma unroll
            for (int off = 1; off < 32; off <<= 1) {
                int y = __shfl_up_sync(0xffffffffu, z, off);
                if (lane >= off) z += y;
            }
            warpsums[lane] = z;
        }
        __syncthreads();
        int pref = (wid > 0) ? warpsums[wid - 1] : 0;
        int excl = carry + pref + x - v;
        if (idx < Nn) { rowptr[idx] = excl; cursor[idx] = excl; }
        carry += warpsums[31];
        __syncthreads();
    }
    if (tid == 0) rowptr[Nn] = carry;
}

__global__ void fill_kernel(const int* __restrict__ ei, long long E,
                            int* __restrict__ cursor, int* __restrict__ esrc) {
    long long e = (long long)blockIdx.x * blockDim.x + threadIdx.x;
    if (e >= E) return;
    int s = ei[e];
    int d = ei[E + e];
    int p = atomicAdd(&cursor[d], 1);
    esrc[p] = s;
}

// ---------------- generic bf16-split GEMM with ldmatrix (embed only) ----------
__global__ __launch_bounds__(256)
void mma_gemm_kernel(const uint32_t* __restrict__ AH, const uint32_t* __restrict__ AL,
                     int KP, int Apitch,
                     const uint32_t* __restrict__ BTH, const uint32_t* __restrict__ BTL,
                     int Bpitch,
                     float* __restrict__ C, int M, int N, int act,
                     uint32_t* __restrict__ outH, uint32_t* __restrict__ outL, int opitch) {
    __shared__ uint32_t AsH[128 * 20];
    __shared__ uint32_t AsL[128 * 20];
    __shared__ uint32_t BsH[128 * 20];
    __shared__ uint32_t BsL[128 * 20];

    const int tid  = threadIdx.x;
    const int lane = tid & 31;
    const int warp = tid >> 5;
    const int warpM = warp >> 2;
    const int warpN = warp & 3;
    const int row0 = blockIdx.y * 128;
    const int col0 = blockIdx.x * 128;

    const uint32_t aHb = (uint32_t)__cvta_generic_to_shared(AsH);
    const uint32_t aLb = (uint32_t)__cvta_generic_to_shared(AsL);
    const uint32_t bHb = (uint32_t)__cvta_generic_to_shared(BsH);
    const uint32_t bLb = (uint32_t)__cvta_generic_to_shared(BsL);

    const int lr   = tid >> 2;
    const int lkp4 = (tid & 3) * 4;
    const int a_lane_off = (lane & 15) * 20 + ((lane >> 4) << 2);
    const int b_lane_off = ((lane & 7) + ((lane >> 4) << 3)) * 20 + (((lane >> 3) & 1) << 2);

    float acc[4][4][4];
#pragma unroll
    for (int mi = 0; mi < 4; mi++)
#pragma unroll
        for (int ni = 0; ni < 4; ni++)
#pragma unroll
            for (int q = 0; q < 4; q++) acc[mi][ni][q] = 0.0f;

    const int ntiles = (KP + 15) >> 4;

    for (int t = 0; t < ntiles; t++) {
        const int ktp = t * 16;
#pragma unroll
        for (int i = 0; i < 2; i++) {
            int r  = lr + i * 64;
            int gr = row0 + r;
            uint4 vh = make_uint4(0, 0, 0, 0);
            uint4 vl = make_uint4(0, 0, 0, 0);
            if (gr < M) {
                long long off = (long long)gr * Apitch + ktp + lkp4;
                vh = *(const uint4*)&AH[off];
                vl = *(const uint4*)&AL[off];
            }
            *(uint4*)&AsH[r * 20 + lkp4] = vh;
            *(uint4*)&AsL[r * 20 + lkp4] = vl;
        }
#pragma unroll
        for (int i = 0; i < 2; i++) {
            int r = lr + i * 64;
            long long off = (long long)(col0 + r) * Bpitch + ktp + lkp4;
            *(uint4*)&BsH[r * 20 + lkp4] = *(const uint4*)&BTH[off];
            *(uint4*)&BsL[r * 20 + lkp4] = *(const uint4*)&BTL[off];
        }
        __syncthreads();

#pragma unroll
        for (int ks = 0; ks < 2; ks++) {
            const int kp0 = ks * 8;
            uint32_t bfh[4][2], bfl[4][2];
#pragma unroll
            for (int ni2 = 0; ni2 < 2; ni2++) {
                uint32_t off = (uint32_t)(((warpN * 32 + ni2 * 16) * 20 + kp0 + b_lane_off) * 4);
                ldsm4(bfh[ni2 * 2][0], bfh[ni2 * 2][1],
                      bfh[ni2 * 2 + 1][0], bfh[ni2 * 2 + 1][1], bHb + off);
                ldsm4(bfl[ni2 * 2][0], bfl[ni2 * 2][1],
                      bfl[ni2 * 2 + 1][0], bfl[ni2 * 2 + 1][1], bLb + off);
            }
#pragma unroll
            for (int mi = 0; mi < 4; mi++) {
                uint32_t off = (uint32_t)(((warpM * 64 + mi * 16) * 20 + kp0 + a_lane_off) * 4);
                uint32_t afh[4], afl[4];
                ldsm4(afh[0], afh[1], afh[2], afh[3], aHb + off);
                ldsm4(afl[0], afl[1], afl[2], afl[3], aLb + off);
#pragma unroll
                for (int ni = 0; ni < 4; ni++) {
                    mma_bf16(acc[mi][ni], afh, bfl[ni]);
                    mma_bf16(acc[mi][ni], afl, bfh[ni]);
                    mma_bf16(acc[mi][ni], afh, bfh[ni]);
                }
            }
        }
        __syncthreads();
    }

#pragma unroll
    for (int mi = 0; mi < 4; mi++) {
#pragma unroll
        for (int ni = 0; ni < 4; ni++) {
            int c = col0 + warpN * 32 + ni * 8 + (lane & 3) * 2;
#pragma unroll
            for (int half = 0; half < 2; half++) {
                int r = row0 + warpM * 64 + mi * 16 + (lane >> 2) + half * 8;
                if (r >= M) continue;
                float v0 = acc[mi][ni][half * 2 + 0];
                float v1 = acc[mi][ni][half * 2 + 1];
                if (act == 1) { v0 = tanhf(v0); v1 = tanhf(v1); }
                if (C != nullptr)
                    *(float2*)(C + (long long)r * N + c) = make_float2(v0, v1);
                if (outH != nullptr) {
                    uint32_t hh, ll;
                    split2(v0, v1, hh, ll);
                    outH[(long long)r * opitch + (c >> 1)] = hh;
                    outL[(long long)r * opitch + (c >> 1)] = ll;
                }
            }
        }
    }
}

// ---------------- fused step GEMM + GRU gate (64-col tile, 3 CTA/SM) ----------
// Block tile 128 rows x 64 permuted cols. B resident (64 cols x 64 kpairs per
// bhalf). Warp tile 64x16 (ni0 = full-K gate r/z, ni1 = half-K gate i/h).
// Epilogue stages pre-activations (+bias) through smem, then applies GRU.
#define FS_SMEM ((2 * 64 * 68 + 2 * 128 * 20) * 4)

__global__ __launch_bounds__(256, 3)
void fused_step_kernel(const uint32_t* __restrict__ hsH, const uint32_t* __restrict__ hsL,
                       const uint32_t* __restrict__ hH, const uint32_t* __restrict__ hL,
                       const uint32_t* __restrict__ BTH, const uint32_t* __restrict__ BTL,
                       const float* __restrict__ bcat,
                       uint32_t* __restrict__ hHn, uint32_t* __restrict__ hLn,
                       int M) {
    extern __shared__ uint32_t smem[];
    uint32_t* BsH = smem;                        // [64][68]
    uint32_t* BsL = smem + 64 * 68;
    uint32_t* AsH = smem + 2 * 64 * 68;          // [128][20]
    uint32_t* AsL = smem + 2 * 64 * 68 + 128 * 20;
    float* stage = (float*)smem;                 // [128][65], aliases after mainloop

    const int tid  = threadIdx.x;
    const int lane = tid & 31;
    const int warp = tid >> 5;
    const int warpM = warp >> 2;
    const int warpN = warp & 3;
    const int row0 = blockIdx.y * 128;
    const int bx   = blockIdx.x;                 // 0..7

    const uint32_t aHb = (uint32_t)__cvta_generic_to_shared(AsH);
    const uint32_t aLb = (uint32_t)__cvta_generic_to_shared(AsL);
    const uint32_t bHb = (uint32_t)__cvta_generic_to_shared(BsH);
    const uint32_t bLb = (uint32_t)__cvta_generic_to_shared(BsL);

    const int lr   = tid >> 2;                   // 0..63
    const int lkp4 = (tid & 3) * 4;
    const int a_lane_off = (lane & 15) * 20 + ((lane >> 4) << 2);
    const int b_lane_off = ((lane & 7) + ((lane >> 4) << 3)) * 68 + (((lane >> 3) & 1) << 2);

    float acc[4][2][4];
#pragma unroll
    for (int mi = 0; mi < 4; mi++)
#pragma unroll
        for (int ni = 0; ni < 2; ni++)
#pragma unroll
            for (int q = 0; q < 4; q++) acc[mi][ni][q] = 0.0f;

    // ---- two phases: bhalf 0 (A=hsum), bhalf 1 (A=h) ----
#pragma unroll
    for (int bhalf = 0; bhalf < 2; bhalf++) {
        // B load: 64 cols x 64 kpairs for this half
#pragma unroll
        for (int kk = 0; kk < 4; kk++) {
            int kp = lkp4 + kk * 16;
            long long off = (long long)(bx * 64 + lr) * 128 + bhalf * 64 + kp;
            *(uint4*)&BsH[lr * 68 + kp] = *(const uint4*)&BTH[off];
            *(uint4*)&BsL[lr * 68 + kp] = *(const uint4*)&BTL[off];
        }
        const uint32_t* srcH = bhalf ? hH : hsH;
        const uint32_t* srcL = bhalf ? hL : hsL;
        const bool ni1_active = ((warpN & 1) == bhalf);

        for (int tt = 0; tt < 4; tt++) {
            const int ktp_loc = tt * 16;
#pragma unroll
            for (int i = 0; i < 2; i++) {
                int r  = lr + i * 64;
                int gr = row0 + r;
                uint4 vh = make_uint4(0, 0, 0, 0);
                uint4 vl = make_uint4(0, 0, 0, 0);
                if (gr < M) {
                    long long off = (long long)gr * 64 + ktp_loc + lkp4;
                    vh = *(const uint4*)&srcH[off];
                    vl = *(const uint4*)&srcL[off];
                }
                *(uint4*)&AsH[r * 20 + lkp4] = vh;
                *(uint4*)&AsL[r * 20 + lkp4] = vl;
            }
            __syncthreads();

#pragma unroll
            for (int ks = 0; ks < 2; ks++) {
                const int kp0 = ks * 8;
                const int kpb = tt * 16 + kp0;
                uint32_t bfh[2][2], bfl[2][2];
                {
                    uint32_t off = (uint32_t)(((warpN * 16) * 68 + kpb + b_lane_off) * 4);
                    ldsm4(bfh[0][0], bfh[0][1], bfh[1][0], bfh[1][1], bHb + off);
                    ldsm4(bfl[0][0], bfl[0][1], bfl[1][0], bfl[1][1], bLb + off);
                }
#pragma unroll
                for (int mi = 0; mi < 4; mi++) {
                    uint32_t off = (uint32_t)(((warpM * 64 + mi * 16) * 20 + kp0 + a_lane_off) * 4);
                    uint32_t afh[4], afl[4];
                    ldsm4(afh[0], afh[1], afh[2], afh[3], aHb + off);
                    ldsm4(afl[0], afl[1], afl[2], afl[3], aLb + off);
                    // ni0: full-K gate (r or z)
                    mma_bf16(acc[mi][0], afh, bfl[0]);
                    mma_bf16(acc[mi][0], afl, bfh[0]);
                    mma_bf16(acc[mi][0], afh, bfh[0]);
                    // ni1: half-K gate (i_n on hsum half / h_n on h half)
                    if (ni1_active) {
                        mma_bf16(acc[mi][1], afh, bfl[1]);
                        mma_bf16(acc[mi][1], afl, bfh[1]);
                        mma_bf16(acc[mi][1], afh, bfh[1]);
                    }
                }
            }
            __syncthreads();
        }
    }

    // ---- stage pre-activations (+bias) into smem ----
    float bc[2][2];
#pragma unroll
    for (int ni = 0; ni < 2; ni++) {
        int C = bx * 64 + warpN * 16 + ni * 8 + (lane & 3) * 2;
        bc[ni][0] = bcat[C];
        bc[ni][1] = bcat[C + 1];
    }
    // mainloop ended with __syncthreads(): safe to overwrite smem
#pragma unroll
    for (int mi = 0; mi < 4; mi++) {
#pragma unroll
        for (int ni = 0; ni < 2; ni++) {
#pragma unroll
            for (int half = 0; half < 2; half++) {
                int row = warpM * 64 + mi * 16 + (lane >> 2) + half * 8;
                int col = warpN * 16 + ni * 8 + (lane & 3) * 2;
                stage[row * 65 + col]     = acc[mi][ni][half * 2 + 0] + bc[ni][0];
                stage[row * 65 + col + 1] = acc[mi][ni][half * 2 + 1] + bc[ni][1];
            }
        }
    }
    __syncthreads();

    // ---- GRU epilogue: 128 rows x 8 h-pairs, 4 pairs per thread ----
#pragma unroll
    for (int k = 0; k < 4; k++) {
        int p = tid + k * 256;            // 0..1023
        int row = p & 127;
        int jp  = p >> 7;                 // h-pair index 0..7
        int rg = row0 + row;
        if (rg >= M) continue;
        int j0 = jp * 2;
        int q  = j0 >> 3;
        int w0 = j0 & 7;
        const float* st = stage + row * 65 + q * 32 + w0;
        float rp0 = st[0],  rp1 = st[1];      // r @ group offset 0
        float ip0 = st[8],  ip1 = st[9];      // i @ +8
        float zp0 = st[16], zp1 = st[17];     // z @ +16
        float hp0 = st[24], hp1 = st[25];     // h @ +24
        long long hb = (long long)rg * 64 + bx * 8 + jp;
        float ho0, ho1;
        unsplit2(hH[hb], hL[hb], ho0, ho1);
        float hn0, hn1;
        {
            float rr = sigmoidf_(rp0), zz = sigmoidf_(zp0);
            float cand = tanhf(ip0 + rr * hp0);
            hn0 = (1.0f - zz) * cand + zz * ho0;
        }
        {
            float rr = sigmoidf_(rp1), zz = sigmoidf_(zp1);
            float cand = tanhf(ip1 + rr * hp1);
            hn1 = (1.0f - zz) * cand + zz * ho1;
        }
        uint32_t hh, ll;
        split2(hn0, hn1, hh, ll);
        hHn[hb] = hh;
        hLn[hb] = ll;
    }
}

// ---------------- CSR gather-reduce: hsum[n] = sum_{e: dst=n} h[src_e] -------
__global__ void gather_kernel(const int* __restrict__ rowptr,
                              const int* __restrict__ esrc,
                              const uint32_t* __restrict__ hH,
                              const uint32_t* __restrict__ hL,
                              uint32_t* __restrict__ hsH, uint32_t* __restrict__ hsL,
                              int Nn) {
    int w = (int)(((long long)blockIdx.x * blockDim.x + threadIdx.x) >> 5);
    int lane = threadIdx.x & 31;
    if (w >= Nn) return;
    int i = rowptr[w];
    const int end = rowptr[w + 1];
    const int u = lane * 2;
    float a0 = 0.f, a1 = 0.f, a2 = 0.f, a3 = 0.f;
    int s0 = (i < end) ? esrc[i] : 0;
    int s1 = (i + 1 < end) ? esrc[i + 1] : 0;
    while (i < end) {
        int s = s0;
        s0 = s1;
        s1 = (i + 2 < end) ? esrc[i + 2] : 0;
        uint2 vh = *(const uint2*)&hH[(long long)s * 64 + u];
        uint2 vl = *(const uint2*)&hL[(long long)s * 64 + u];
        float x0, y0, x1, y1;
        unsplit2(vh.x, vl.x, x0, y0);
        unsplit2(vh.y, vl.y, x1, y1);
        a0 += x0; a1 += y0; a2 += x1; a3 += y1;
        i++;
    }
    uint32_t h0, l0, h1, l1;
    split2(a0, a1, h0, l0);
    split2(a2, a3, h1, l1);
    long long b = (long long)w * 64 + u;
    hsH[b] = h0; hsH[b + 1] = h1;
    hsL[b] = l0; hsL[b + 1] = l1;
}

// ---------------- sorted-batch pooling + head ---------------------------------
__global__ void find_starts_kernel(const int* __restrict__ batch, int Nn, int G,
                                   int* __restrict__ starts) {
    int g = blockIdx.x * blockDim.x + threadIdx.x;
    if (g > G) return;
    if (g == G) { starts[G] = Nn; return; }
    int lo = 0, hi = Nn;
    while (lo < hi) {
        int mid = (lo + hi) >> 1;
        if (batch[mid] < g) lo = mid + 1; else hi = mid;
    }
    starts[g] = lo;
}

// 512 threads: 4 node-striped subsets of 128 feature-lanes, then smem reduce.
__global__ void pool_final_kernel(const uint32_t* __restrict__ hH,
                                  const uint32_t* __restrict__ hL,
                                  const int* __restrict__ starts,
                                  const float* __restrict__ w_pred,
                                  const float* __restrict__ b_pred,
                                  float* __restrict__ out) {
    __shared__ float part[4][128];
    __shared__ float ws[4];
    int g = blockIdx.x;
    int t = threadIdx.x & 127;     // feature index
    int sub = threadIdx.x >> 7;    // 0..3
    int s = starts[g], e = starts[g + 1];
    int u = t >> 1;
    int half = t & 1;
    float acc = 0.0f;
    for (int n = s + sub; n < e; n += 4) {
        uint32_t hh = hH[(long long)n * 64 + u];
        uint32_t ll = hL[(long long)n * 64 + u];
        float a, bq;
        unsplit2(hh, ll, a, bq);
        acc += half ? bq : a;
    }
    part[sub][t] = acc;
    __syncthreads();
    if (threadIdx.x < 128) {
        float total = part[0][t] + part[1][t] + part[2][t] + part[3][t];
        float c = fmaxf((float)(e - s), 1.0f);
        float v = fmaxf(total / c, 0.0f) * w_pred[t];
#pragma unroll
        for (int o = 16; o > 0; o >>= 1) v += __shfl_down_sync(0xffffffffu, v, o);
        if ((t & 31) == 0) ws[t >> 5] = v;
    }
    __syncthreads();
    if (threadIdx.x == 0) out[g] = ws[0] + ws[1] + ws[2] + ws[3] + b_pred[0];
}

// ---------------- host launcher -----------------------------------------------
extern "C" void kernel_launch(void* const* d_in, const int* in_sizes, int n_in,
                              void* d_out, int out_size) {
    const float* x       = (const float*)d_in[0];
    const int*   ei      = (const int*)d_in[1];
    const int*   batch   = (const int*)d_in[2];
    const float* W_embed = (const float*)d_in[3];
    const float* W_mpnn  = (const float*)d_in[4];
    const float* w_ih    = (const float*)d_in[5];
    const float* w_hh    = (const float*)d_in[6];
    const float* b_ih    = (const float*)d_in[7];
    const float* b_hh    = (const float*)d_in[8];
    const float* w_pred  = (const float*)d_in[9];
    const float* b_pred  = (const float*)d_in[10];
    float* out = (float*)d_out;

    int Nn = in_sizes[2];
    long long E = in_sizes[1] / 2;
    int steps = in_sizes[4] / (HID * HID);
    int F  = in_sizes[0] / Nn;      // 92
    int G = out_size;
    int KPx = F / 2;                 // 46
    int Apx = (KPx + 15) & ~15;      // 48

    cudaFuncSetAttribute(fused_step_kernel,
                         cudaFuncAttributeMaxDynamicSharedMemorySize, FS_SMEM);

    float *p_bcat, *p_Wfold;
    uint32_t *p_hHa, *p_hLa, *p_hHb, *p_hLb, *p_hsH, *p_hsL, *p_xH, *p_xL;
    uint32_t *p_BgTH, *p_BgTL, *p_WembTH, *p_WembTL;
    int *p_deg, *p_rowptr, *p_cursor, *p_esrc, *p_starts;
    cudaGetSymbolAddress((void**)&p_bcat,   g_bcat);
    cudaGetSymbolAddress((void**)&p_Wfold,  g_Wfold);
    cudaGetSymbolAddress((void**)&p_hHa,    g_hHa);
    cudaGetSymbolAddress((void**)&p_hLa,    g_hLa);
    cudaGetSymbolAddress((void**)&p_hHb,    g_hHb);
    cudaGetSymbolAddress((void**)&p_hLb,    g_hLb);
    cudaGetSymbolAddress((void**)&p_hsH,    g_hsH);
    cudaGetSymbolAddress((void**)&p_hsL,    g_hsL);
    cudaGetSymbolAddress((void**)&p_xH,     g_xH);
    cudaGetSymbolAddress((void**)&p_xL,     g_xL);
    cudaGetSymbolAddress((void**)&p_BgTH,   g_BgTH);
    cudaGetSymbolAddress((void**)&p_BgTL,   g_BgTL);
    cudaGetSymbolAddress((void**)&p_WembTH, g_WembTH);
    cudaGetSymbolAddress((void**)&p_WembTL, g_WembTL);
    cudaGetSymbolAddress((void**)&p_deg,    g_deg);
    cudaGetSymbolAddress((void**)&p_rowptr, g_rowptr);
    cudaGetSymbolAddress((void**)&p_cursor, g_cursor);
    cudaGetSymbolAddress((void**)&p_esrc,   g_esrc);
    cudaGetSymbolAddress((void**)&p_starts, g_starts);

    // ---- weight fold + pack ----
    {
        int tf = steps * 128 * 384;
        fold_kernel<<<(tf + 255) / 256, 256>>>(W_mpnn, w_ih, p_Wfold, steps);
        int tb = steps * 512 * 128;
        pack_BgT_kernel<<<(tb + 255) / 256, 256>>>(p_Wfold, w_hh, p_BgTH, p_BgTL, steps);
        pack_bcat_kernel<<<2, 256>>>(b_ih, b_hh, p_bcat);
        pack_wembT_kernel<<<(128 * 48 + 255) / 256, 256>>>(W_embed, p_WembTH, p_WembTL, KPx);
        long long tx = (long long)Nn * Apx;
        split_x_kernel<<<(int)((tx + 255) / 256), 256>>>(x, p_xH, p_xL, Nn, F, KPx, Apx);
    }

    // ---- CSR build + graph starts ----
    zero_i<<<(Nn + 255) / 256, 256>>>(p_deg, Nn);
    hist_kernel<<<(int)((E + 255) / 256), 256>>>(ei, E, p_deg);
    scan_kernel<<<1, 1024>>>(p_deg, p_rowptr, p_cursor, Nn);
    fill_kernel<<<(int)((E + 255) / 256), 256>>>(ei, E, p_cursor, p_esrc);
    find_starts_kernel<<<(G + 256) / 256, 256>>>(batch, Nn, G, p_starts);

    int mt = (Nn + 127) / 128;

    // ---- embed: h = tanh(x @ W_embed) -> split h (buffer A) ----
    mma_gemm_kernel<<<dim3(1, mt), 256>>>(
        p_xH, p_xL, KPx, Apx, p_WembTH, p_WembTL, 48,
        nullptr, Nn, HID, 1, p_hHa, p_hLa, 64);

    uint32_t *curH = p_hHa, *curL = p_hLa;
    uint32_t *nxtH = p_hHb, *nxtL = p_hLb;

    for (int s = 0; s < steps; s++) {
        gather_kernel<<<(int)(((long long)Nn * 32 + 255) / 256), 256>>>(
            p_rowptr, p_esrc, curH, curL, p_hsH, p_hsL, Nn);

        fused_step_kernel<<<dim3(8, mt), 256, FS_SMEM>>>(
            p_hsH, p_hsL, curH, curL,
            p_BgTH + (long long)s * 512 * 128, p_BgTL + (long long)s * 512 * 128,
            p_bcat, nxtH, nxtL, Nn);

        uint32_t* t;
        t = curH; curH = nxtH; nxtH = t;
        t = curL; curL = nxtL; nxtL = t;
    }

    pool_final_kernel<<<G, 512>>>(curH, curL, p_starts, w_pred, b_pred, out);
}

// round 16
// speedup vs baseline: 1.4657x; 1.4657x over previous
#include <cuda_runtime.h>
#include <cuda_bf16.h>
#include <math.h>
#include <stdint.h>

#define HID 128
#define MAX_N 100352
#define MAXSTEPS 8
#define NG 256
#define MAX_E 2000000

// ---------------- scratch (static device globals; no runtime allocation) ----
__device__ __align__(16) uint32_t g_hHa [MAX_N * 64];      // ping-pong h splits
__device__ __align__(16) uint32_t g_hLa [MAX_N * 64];
__device__ __align__(16) uint32_t g_hHb [MAX_N * 64];
__device__ __align__(16) uint32_t g_hLb [MAX_N * 64];
__device__ __align__(16) uint32_t g_hsH [MAX_N * 64];      // hsum split
__device__ __align__(16) uint32_t g_hsL [MAX_N * 64];
__device__ __align__(16) uint32_t g_xH  [MAX_N * 48];
__device__ __align__(16) uint32_t g_xL  [MAX_N * 48];
__device__ __align__(16) float    g_Wfold[MAXSTEPS * 128 * 384];   // W_mpnn[s] @ w_ih^T
__device__ __align__(16) uint32_t g_BgTH[MAXSTEPS * 512 * 128];    // permuted B'' split
__device__ __align__(16) uint32_t g_BgTL[MAXSTEPS * 512 * 128];
__device__ __align__(16) uint32_t g_WembTH[128 * 48];
__device__ __align__(16) uint32_t g_WembTL[128 * 48];
__device__ __align__(16) float    g_bcat[512];             // permuted bias
__device__ int g_deg[MAX_N];
__device__ int g_rowptr[MAX_N + 1];
__device__ int g_cursor[MAX_N];
__device__ int g_esrc[MAX_E];
__device__ int g_starts[NG + 1];

// ---------------- helpers ----------------------------------------------------
__device__ __forceinline__ void split2(float x, float y, uint32_t& hi, uint32_t& lo) {
    __nv_bfloat16 hx = __float2bfloat16_rn(x);
    __nv_bfloat16 hy = __float2bfloat16_rn(y);
    float rx = x - __bfloat162float(hx);
    float ry = y - __bfloat162float(hy);
    __nv_bfloat162 h; h.x = hx; h.y = hy;
    __nv_bfloat162 l; l.x = __float2bfloat16_rn(rx); l.y = __float2bfloat16_rn(ry);
    hi = *(uint32_t*)&h;
    lo = *(uint32_t*)&l;
}

__device__ __forceinline__ void unsplit2(uint32_t hi, uint32_t lo, float& x, float& y) {
    __nv_bfloat162 h = *(__nv_bfloat162*)&hi;
    __nv_bfloat162 l = *(__nv_bfloat162*)&lo;
    x = __bfloat162float(h.x) + __bfloat162float(l.x);
    y = __bfloat162float(h.y) + __bfloat162float(l.y);
}

__device__ __forceinline__ void mma_bf16(float* c, const uint32_t* a, const uint32_t* b) {
    asm volatile(
        "mma.sync.aligned.m16n8k16.row.col.f32.bf16.bf16.f32 "
        "{%0,%1,%2,%3}, {%4,%5,%6,%7}, {%8,%9}, {%0,%1,%2,%3};\n"
        : "+f"(c[0]), "+f"(c[1]), "+f"(c[2]), "+f"(c[3])
        : "r"(a[0]), "r"(a[1]), "r"(a[2]), "r"(a[3]),
          "r"(b[0]), "r"(b[1]));
}

__device__ __forceinline__ void ldsm4(uint32_t& r0, uint32_t& r1,
                                      uint32_t& r2, uint32_t& r3, uint32_t addr) {
    asm volatile("ldmatrix.sync.aligned.m8n8.x4.shared.b16 {%0,%1,%2,%3}, [%4];"
                 : "=r"(r0), "=r"(r1), "=r"(r2), "=r"(r3) : "r"(addr));
}

__device__ __forceinline__ float sigmoidf_(float x) {
    return 1.0f / (1.0f + expf(-x));
}

// ---------------- small utility kernels --------------------------------------
__global__ void zero_i(int* p, int n) {
    int i = blockIdx.x * blockDim.x + threadIdx.x;
    if (i < n) p[i] = 0;
}

// ---------------- weight fold / pack kernels ----------------------------------
// Wfold[s] = W_mpnn[s] @ w_ih^T   : [128 K][384 cols]
__global__ void fold_kernel(const float* __restrict__ Wm,
                            const float* __restrict__ wih,
                            float* __restrict__ Wfold, int steps) {
    int idx = blockIdx.x * blockDim.x + threadIdx.x;
    int total = steps * 128 * 384;
    if (idx >= total) return;
    int s = idx / (128 * 384);
    int rem = idx % (128 * 384);
    int k = rem / 384;
    int j = rem % 384;
    const float* wr = Wm + s * 128 * 128 + k * 128;
    const float* ir = wih + j * 128;
    float acc = 0.0f;
#pragma unroll 8
    for (int c = 0; c < 128; c++) acc = fmaf(wr[c], ir[c], acc);
    Wfold[idx] = acc;
}

// permuted B'': reordered col C in [0,512): comp=(C>>3)&3,
// hidx = (C>>7)*32 + ((C>>5)&3)*8 + (C&7). K=[hsum kpairs 0..63 | h kpairs 64..127].
// comp0=r_sum, comp1=z_sum, comp2=i_n (hsum half only), comp3=h_n (h half only).
__global__ void pack_BgT_kernel(const float* __restrict__ Wfold,
                                const float* __restrict__ whh,
                                uint32_t* __restrict__ WH, uint32_t* __restrict__ WL,
                                int steps) {
    int idx = blockIdx.x * blockDim.x + threadIdx.x;
    int total = steps * 512 * 128;
    if (idx >= total) return;
    int s = idx / (512 * 128);
    int rem = idx % (512 * 128);
    int C = rem / 128;
    int p = rem % 128;
    int comp = (C >> 3) & 3;
    int hidx = (C >> 7) * 32 + ((C >> 5) & 3) * 8 + (C & 7);
    float a = 0.f, b = 0.f;
    if (p < 64) {                      // hsum half: Wfold cols (comp<3)
        int k0 = 2 * p;
        if (comp < 3) {
            int j = comp * 128 + hidx;
            a = Wfold[s * 128 * 384 + k0 * 384 + j];
            b = Wfold[s * 128 * 384 + (k0 + 1) * 384 + j];
        }
    } else {                           // h half: w_hh rows
        int k0 = 2 * (p - 64);
        int jj = -1;
        if (comp == 0)      jj = hidx;
        else if (comp == 1) jj = 128 + hidx;
        else if (comp == 3) jj = 256 + hidx;
        if (jj >= 0) { a = whh[jj * HID + k0]; b = whh[jj * HID + k0 + 1]; }
    }
    uint32_t h, l;
    split2(a, b, h, l);
    WH[idx] = h; WL[idx] = l;
}

__global__ void pack_bcat_kernel(const float* __restrict__ bih,
                                 const float* __restrict__ bhh,
                                 float* __restrict__ bcat) {
    int C = blockIdx.x * blockDim.x + threadIdx.x;
    if (C >= 512) return;
    int comp = (C >> 3) & 3;
    int hidx = (C >> 7) * 32 + ((C >> 5) & 3) * 8 + (C & 7);
    float v;
    if (comp == 0)      v = bih[hidx] + bhh[hidx];
    else if (comp == 1) v = bih[128 + hidx] + bhh[128 + hidx];
    else if (comp == 2) v = bih[256 + hidx];
    else                v = bhh[256 + hidx];
    bcat[C] = v;
}

__global__ void pack_wembT_kernel(const float* __restrict__ We,
                                  uint32_t* __restrict__ WH, uint32_t* __restrict__ WL,
                                  int KPx) {
    int idx = blockIdx.x * blockDim.x + threadIdx.x;
    if (idx >= 128 * 48) return;
    int j = idx / 48;
    int p = idx % 48;
    uint32_t h = 0, l = 0;
    if (p < KPx) split2(We[(2 * p) * HID + j], We[(2 * p + 1) * HID + j], h, l);
    WH[idx] = h; WL[idx] = l;
}

__global__ void split_x_kernel(const float* __restrict__ x,
                               uint32_t* __restrict__ xH, uint32_t* __restrict__ xL,
                               int Nn, int F, int KPx, int Apx) {
    long long idx = (long long)blockIdx.x * blockDim.x + threadIdx.x;
    if (idx >= (long long)Nn * Apx) return;
    int n = (int)(idx / Apx);
    int p = (int)(idx % Apx);
    uint32_t h = 0, l = 0;
    if (p < KPx) split2(x[(long long)n * F + 2 * p], x[(long long)n * F + 2 * p + 1], h, l);
    xH[idx] = h; xL[idx] = l;
}

// ---------------- CSR build ---------------------------------------------------
__global__ void hist_kernel(const int* __restrict__ ei, long long E, int* __restrict__ deg) {
    long long e = (long long)blockIdx.x * blockDim.x + threadIdx.x;
    if (e >= E) return;
    atomicAdd(&deg[ei[E + e]], 1);
}

__global__ void scan_kernel(const int* __restrict__ deg, int* __restrict__ rowptr,
                            int* __restrict__ cursor, int Nn) {
    __shared__ int warpsums[32];
    const int tid = threadIdx.x;
    const int lane = tid & 31;
    const int wid = tid >> 5;
    int carry = 0;
    for (int base = 0; base < Nn; base += 1024) {
        int idx = base + tid;
        int v = (idx < Nn) ? deg[idx] : 0;
        int x = v;
#pragma unroll
        for (int off = 1; off < 32; off <<= 1) {
            int y = __shfl_up_sync(0xffffffffu, x, off);
            if (lane >= off) x += y;
        }
        if (lane == 31) warpsums[wid] = x;
        __syncthreads();
        if (wid == 0) {
            int z = warpsums[lane];
#pragma unroll
            for (int off = 1; off < 32; off <<= 1) {
                int y = __shfl_up_sync(0xffffffffu, z, off);
                if (lane >= off) z += y;
            }
            warpsums[lane] = z;
        }
        __syncthreads();
        int pref = (wid > 0) ? warpsums[wid - 1] : 0;
        int excl = carry + pref + x - v;
        if (idx < Nn) { rowptr[idx] = excl; cursor[idx] = excl; }
        carry += warpsums[31];
        __syncthreads();
    }
    if (tid == 0) rowptr[Nn] = carry;
}

__global__ void fill_kernel(const int* __restrict__ ei, long long E,
                            int* __restrict__ cursor, int* __restrict__ esrc) {
    long long e = (long long)blockIdx.x * blockDim.x + threadIdx.x;
    if (e >= E) return;
    int s = ei[e];
    int d = ei[E + e];
    int p = atomicAdd(&cursor[d], 1);
    esrc[p] = s;
}

// ---------------- generic bf16-split GEMM with ldmatrix (embed only) ----------
__global__ __launch_bounds__(256)
void mma_gemm_kernel(const uint32_t* __restrict__ AH, const uint32_t* __restrict__ AL,
                     int KP, int Apitch,
                     const uint32_t* __restrict__ BTH, const uint32_t* __restrict__ BTL,
                     int Bpitch,
                     float* __restrict__ C, int M, int N, int act,
                     uint32_t* __restrict__ outH, uint32_t* __restrict__ outL, int opitch) {
    __shared__ uint32_t AsH[128 * 20];
    __shared__ uint32_t AsL[128 * 20];
    __shared__ uint32_t BsH[128 * 20];
    __shared__ uint32_t BsL[128 * 20];

    const int tid  = threadIdx.x;
    const int lane = tid & 31;
    const int warp = tid >> 5;
    const int warpM = warp >> 2;
    const int warpN = warp & 3;
    const int row0 = blockIdx.y * 128;
    const int col0 = blockIdx.x * 128;

    const uint32_t aHb = (uint32_t)__cvta_generic_to_shared(AsH);
    const uint32_t aLb = (uint32_t)__cvta_generic_to_shared(AsL);
    const uint32_t bHb = (uint32_t)__cvta_generic_to_shared(BsH);
    const uint32_t bLb = (uint32_t)__cvta_generic_to_shared(BsL);

    const int lr   = tid >> 2;
    const int lkp4 = (tid & 3) * 4;
    const int a_lane_off = (lane & 15) * 20 + ((lane >> 4) << 2);
    const int b_lane_off = ((lane & 7) + ((lane >> 4) << 3)) * 20 + (((lane >> 3) & 1) << 2);

    float acc[4][4][4];
#pragma unroll
    for (int mi = 0; mi < 4; mi++)
#pragma unroll
        for (int ni = 0; ni < 4; ni++)
#pragma unroll
            for (int q = 0; q < 4; q++) acc[mi][ni][q] = 0.0f;

    const int ntiles = (KP + 15) >> 4;

    for (int t = 0; t < ntiles; t++) {
        const int ktp = t * 16;
#pragma unroll
        for (int i = 0; i < 2; i++) {
            int r  = lr + i * 64;
            int gr = row0 + r;
            uint4 vh = make_uint4(0, 0, 0, 0);
            uint4 vl = make_uint4(0, 0, 0, 0);
            if (gr < M) {
                long long off = (long long)gr * Apitch + ktp + lkp4;
                vh = *(const uint4*)&AH[off];
                vl = *(const uint4*)&AL[off];
            }
            *(uint4*)&AsH[r * 20 + lkp4] = vh;
            *(uint4*)&AsL[r * 20 + lkp4] = vl;
        }
#pragma unroll
        for (int i = 0; i < 2; i++) {
            int r = lr + i * 64;
            long long off = (long long)(col0 + r) * Bpitch + ktp + lkp4;
            *(uint4*)&BsH[r * 20 + lkp4] = *(const uint4*)&BTH[off];
            *(uint4*)&BsL[r * 20 + lkp4] = *(const uint4*)&BTL[off];
        }
        __syncthreads();

#pragma unroll
        for (int ks = 0; ks < 2; ks++) {
            const int kp0 = ks * 8;
            uint32_t bfh[4][2], bfl[4][2];
#pragma unroll
            for (int ni2 = 0; ni2 < 2; ni2++) {
                uint32_t off = (uint32_t)(((warpN * 32 + ni2 * 16) * 20 + kp0 + b_lane_off) * 4);
                ldsm4(bfh[ni2 * 2][0], bfh[ni2 * 2][1],
                      bfh[ni2 * 2 + 1][0], bfh[ni2 * 2 + 1][1], bHb + off);
                ldsm4(bfl[ni2 * 2][0], bfl[ni2 * 2][1],
                      bfl[ni2 * 2 + 1][0], bfl[ni2 * 2 + 1][1], bLb + off);
            }
#pragma unroll
            for (int mi = 0; mi < 4; mi++) {
                uint32_t off = (uint32_t)(((warpM * 64 + mi * 16) * 20 + kp0 + a_lane_off) * 4);
                uint32_t afh[4], afl[4];
                ldsm4(afh[0], afh[1], afh[2], afh[3], aHb + off);
                ldsm4(afl[0], afl[1], afl[2], afl[3], aLb + off);
#pragma unroll
                for (int ni = 0; ni < 4; ni++) {
                    mma_bf16(acc[mi][ni], afh, bfl[ni]);
                    mma_bf16(acc[mi][ni], afl, bfh[ni]);
                    mma_bf16(acc[mi][ni], afh, bfh[ni]);
                }
            }
        }
        __syncthreads();
    }

#pragma unroll
    for (int mi = 0; mi < 4; mi++) {
#pragma unroll
        for (int ni = 0; ni < 4; ni++) {
            int c = col0 + warpN * 32 + ni * 8 + (lane & 3) * 2;
#pragma unroll
            for (int half = 0; half < 2; half++) {
                int r = row0 + warpM * 64 + mi * 16 + (lane >> 2) + half * 8;
                if (r >= M) continue;
                float v0 = acc[mi][ni][half * 2 + 0];
                float v1 = acc[mi][ni][half * 2 + 1];
                if (act == 1) { v0 = tanhf(v0); v1 = tanhf(v1); }
                if (C != nullptr)
                    *(float2*)(C + (long long)r * N + c) = make_float2(v0, v1);
                if (outH != nullptr) {
                    uint32_t hh, ll;
                    split2(v0, v1, hh, ll);
                    outH[(long long)r * opitch + (c >> 1)] = hh;
                    outL[(long long)r * opitch + (c >> 1)] = ll;
                }
            }
        }
    }
}

// ---------------- fused step GEMM + GRU gate (R14 configuration) --------------
// B-half resident in smem (64 kpairs, pitch 68); A tiled 16 kpairs (pitch 20).
#define GIGH_SMEM ((2 * 128 * 68 + 2 * 128 * 20) * 4)

__global__ __launch_bounds__(256)
void fused_step_kernel(const uint32_t* __restrict__ hsH, const uint32_t* __restrict__ hsL,
                       const uint32_t* __restrict__ hH, const uint32_t* __restrict__ hL,
                       const uint32_t* __restrict__ BTH, const uint32_t* __restrict__ BTL,
                       const float* __restrict__ bcat,
                       uint32_t* __restrict__ hHn, uint32_t* __restrict__ hLn,
                       int M) {
    extern __shared__ uint32_t smem[];
    uint32_t* BsH = smem;                        // [128][68]
    uint32_t* BsL = smem + 128 * 68;
    uint32_t* AsH = smem + 2 * 128 * 68;         // [128][20]
    uint32_t* AsL = smem + 2 * 128 * 68 + 128 * 20;

    const int tid  = threadIdx.x;
    const int lane = tid & 31;
    const int warp = tid >> 5;
    const int warpM = warp >> 2;
    const int warpN = warp & 3;
    const int row0 = blockIdx.y * 128;
    const int col0 = blockIdx.x * 128;

    const uint32_t aHb = (uint32_t)__cvta_generic_to_shared(AsH);
    const uint32_t aLb = (uint32_t)__cvta_generic_to_shared(AsL);
    const uint32_t bHb = (uint32_t)__cvta_generic_to_shared(BsH);
    const uint32_t bLb = (uint32_t)__cvta_generic_to_shared(BsL);

    const int lr   = tid >> 2;
    const int lkp4 = (tid & 3) * 4;
    const int a_lane_off = (lane & 15) * 20 + ((lane >> 4) << 2);
    const int b_lane_off = ((lane & 7) + ((lane >> 4) << 3)) * 68 + (((lane >> 3) & 1) << 2);

    float acc[4][4][4];
#pragma unroll
    for (int mi = 0; mi < 4; mi++)
#pragma unroll
        for (int ni = 0; ni < 4; ni++)
#pragma unroll
            for (int q = 0; q < 4; q++) acc[mi][ni][q] = 0.0f;

    // ---- two phases: bhalf 0 (A=hsum, ni 0,1,2) and bhalf 1 (A=h, ni 0,1,3)
#pragma unroll
    for (int bhalf = 0; bhalf < 2; bhalf++) {
        // load resident B half: 128 cols x 64 kpairs
#pragma unroll
        for (int i = 0; i < 2; i++) {
            int col = lr + i * 64;
#pragma unroll
            for (int kk = 0; kk < 4; kk++) {
                int kp = lkp4 + kk * 16;
                long long off = (long long)(col0 + col) * 128 + bhalf * 64 + kp;
                *(uint4*)&BsH[col * 68 + kp] = *(const uint4*)&BTH[off];
                *(uint4*)&BsL[col * 68 + kp] = *(const uint4*)&BTL[off];
            }
        }
        const uint32_t* srcH = bhalf ? hH : hsH;
        const uint32_t* srcL = bhalf ? hL : hsL;

        for (int tt = 0; tt < 4; tt++) {
            const int ktp_loc = tt * 16;
#pragma unroll
            for (int i = 0; i < 2; i++) {
                int r  = lr + i * 64;
                int gr = row0 + r;
                uint4 vh = make_uint4(0, 0, 0, 0);
                uint4 vl = make_uint4(0, 0, 0, 0);
                if (gr < M) {
                    long long off = (long long)gr * 64 + ktp_loc + lkp4;
                    vh = *(const uint4*)&srcH[off];
                    vl = *(const uint4*)&srcL[off];
                }
                *(uint4*)&AsH[r * 20 + lkp4] = vh;
                *(uint4*)&AsL[r * 20 + lkp4] = vl;
            }
            __syncthreads();

#pragma unroll
            for (int ks = 0; ks < 2; ks++) {
                const int kp0 = ks * 8;
                const int kpb = tt * 16 + kp0;
                uint32_t bfh[4][2], bfl[4][2];
#pragma unroll
                for (int ni2 = 0; ni2 < 2; ni2++) {
                    uint32_t off = (uint32_t)(((warpN * 32 + ni2 * 16) * 68 + kpb + b_lane_off) * 4);
                    ldsm4(bfh[ni2 * 2][0], bfh[ni2 * 2][1],
                          bfh[ni2 * 2 + 1][0], bfh[ni2 * 2 + 1][1], bHb + off);
                    ldsm4(bfl[ni2 * 2][0], bfl[ni2 * 2][1],
                          bfl[ni2 * 2 + 1][0], bfl[ni2 * 2 + 1][1], bLb + off);
                }
#pragma unroll
                for (int mi = 0; mi < 4; mi++) {
                    uint32_t off = (uint32_t)(((warpM * 64 + mi * 16) * 20 + kp0 + a_lane_off) * 4);
                    uint32_t afh[4], afl[4];
                    ldsm4(afh[0], afh[1], afh[2], afh[3], aHb + off);
                    ldsm4(afl[0], afl[1], afl[2], afl[3], aLb + off);
#pragma unroll
                    for (int ni = 0; ni < 4; ni++) {
                        // skip structurally-zero blocks: h_n on hsum half, i_n on h half
                        if (bhalf == 0 && ni == 3) continue;
                        if (bhalf == 1 && ni == 2) continue;
                        mma_bf16(acc[mi][ni], afh, bfl[ni]);
                        mma_bf16(acc[mi][ni], afl, bfh[ni]);
                        mma_bf16(acc[mi][ni], afh, bfh[ni]);
                    }
                }
            }
            __syncthreads();
        }
    }

    // ---- fused GRU epilogue ----
    const int c2 = (lane & 3) * 2;
    const int hidx0 = blockIdx.x * 32 + warpN * 8 + c2;
    const int u = hidx0 >> 1;     // u32 pair index within split-h row
    float bc[4][2];
#pragma unroll
    for (int ni = 0; ni < 4; ni++) {
        int C = col0 + warpN * 32 + ni * 8 + c2;
        bc[ni][0] = bcat[C];
        bc[ni][1] = bcat[C + 1];
    }

#pragma unroll
    for (int mi = 0; mi < 4; mi++) {
#pragma unroll
        for (int half = 0; half < 2; half++) {
            int r = row0 + warpM * 64 + mi * 16 + (lane >> 2) + half * 8;
            if (r >= M) continue;
            long long hb = (long long)r * 64 + u;
            float ho0, ho1;
            unsplit2(hH[hb], hL[hb], ho0, ho1);
            float hn0, hn1;
            {
                float rp = acc[mi][0][half * 2 + 0] + bc[0][0];
                float zp = acc[mi][1][half * 2 + 0] + bc[1][0];
                float ip = acc[mi][2][half * 2 + 0] + bc[2][0];
                float hp = acc[mi][3][half * 2 + 0] + bc[3][0];
                float rr = sigmoidf_(rp), zz = sigmoidf_(zp);
                float cand = tanhf(ip + rr * hp);
                hn0 = (1.0f - zz) * cand + zz * ho0;
            }
            {
                float rp = acc[mi][0][half * 2 + 1] + bc[0][1];
                float zp = acc[mi][1][half * 2 + 1] + bc[1][1];
                float ip = acc[mi][2][half * 2 + 1] + bc[2][1];
                float hp = acc[mi][3][half * 2 + 1] + bc[3][1];
                float rr = sigmoidf_(rp), zz = sigmoidf_(zp);
                float cand = tanhf(ip + rr * hp);
                hn1 = (1.0f - zz) * cand + zz * ho1;
            }
            uint32_t hh, ll;
            split2(hn0, hn1, hh, ll);
            hHn[hb] = hh;
            hLn[hb] = ll;
        }
    }
}

// ---------------- CSR gather-reduce (2-edge unrolled for MLP) -----------------
__global__ void gather_kernel(const int* __restrict__ rowptr,
                              const int* __restrict__ esrc,
                              const uint32_t* __restrict__ hH,
                              const uint32_t* __restrict__ hL,
                              uint32_t* __restrict__ hsH, uint32_t* __restrict__ hsL,
                              int Nn) {
    int w = (int)(((long long)blockIdx.x * blockDim.x + threadIdx.x) >> 5);
    int lane = threadIdx.x & 31;
    if (w >= Nn) return;
    int i = rowptr[w];
    const int end = rowptr[w + 1];
    const int u = lane * 2;
    float a0 = 0.f, a1 = 0.f, a2 = 0.f, a3 = 0.f;
    // 2-edge unrolled main loop: 4 independent row loads in flight
    for (; i + 1 < end; i += 2) {
        int sa = esrc[i];
        int sb = esrc[i + 1];
        uint2 vha = *(const uint2*)&hH[(long long)sa * 64 + u];
        uint2 vla = *(const uint2*)&hL[(long long)sa * 64 + u];
        uint2 vhb = *(const uint2*)&hH[(long long)sb * 64 + u];
        uint2 vlb = *(const uint2*)&hL[(long long)sb * 64 + u];
        float x0, y0, x1, y1;
        unsplit2(vha.x, vla.x, x0, y0);
        unsplit2(vha.y, vla.y, x1, y1);
        a0 += x0; a1 += y0; a2 += x1; a3 += y1;
        unsplit2(vhb.x, vlb.x, x0, y0);
        unsplit2(vhb.y, vlb.y, x1, y1);
        a0 += x0; a1 += y0; a2 += x1; a3 += y1;
    }
    if (i < end) {
        int s = esrc[i];
        uint2 vh = *(const uint2*)&hH[(long long)s * 64 + u];
        uint2 vl = *(const uint2*)&hL[(long long)s * 64 + u];
        float x0, y0, x1, y1;
        unsplit2(vh.x, vl.x, x0, y0);
        unsplit2(vh.y, vl.y, x1, y1);
        a0 += x0; a1 += y0; a2 += x1; a3 += y1;
    }
    uint32_t h0, l0, h1, l1;
    split2(a0, a1, h0, l0);
    split2(a2, a3, h1, l1);
    long long b = (long long)w * 64 + u;
    hsH[b] = h0; hsH[b + 1] = h1;
    hsL[b] = l0; hsL[b + 1] = l1;
}

// ---------------- sorted-batch pooling + head ---------------------------------
__global__ void find_starts_kernel(const int* __restrict__ batch, int Nn, int G,
                                   int* __restrict__ starts) {
    int g = blockIdx.x * blockDim.x + threadIdx.x;
    if (g > G) return;
    if (g == G) { starts[G] = Nn; return; }
    int lo = 0, hi = Nn;
    while (lo < hi) {
        int mid = (lo + hi) >> 1;
        if (batch[mid] < g) lo = mid + 1; else hi = mid;
    }
    starts[g] = lo;
}

// 512 threads: 4 node-striped subsets of 128 feature-lanes, then smem reduce.
__global__ void pool_final_kernel(const uint32_t* __restrict__ hH,
                                  const uint32_t* __restrict__ hL,
                                  const int* __restrict__ starts,
                                  const float* __restrict__ w_pred,
                                  const float* __restrict__ b_pred,
                                  float* __restrict__ out) {
    __shared__ float part[4][128];
    __shared__ float ws[4];
    int g = blockIdx.x;
    int t = threadIdx.x & 127;     // feature index
    int sub = threadIdx.x >> 7;    // 0..3
    int s = starts[g], e = starts[g + 1];
    int u = t >> 1;
    int half = t & 1;
    float acc = 0.0f;
    for (int n = s + sub; n < e; n += 4) {
        uint32_t hh = hH[(long long)n * 64 + u];
        uint32_t ll = hL[(long long)n * 64 + u];
        float a, bq;
        unsplit2(hh, ll, a, bq);
        acc += half ? bq : a;
    }
    part[sub][t] = acc;
    __syncthreads();
    if (threadIdx.x < 128) {
        float total = part[0][t] + part[1][t] + part[2][t] + part[3][t];
        float c = fmaxf((float)(e - s), 1.0f);
        float v = fmaxf(total / c, 0.0f) * w_pred[t];
#pragma unroll
        for (int o = 16; o > 0; o >>= 1) v += __shfl_down_sync(0xffffffffu, v, o);
        if ((t & 31) == 0) ws[t >> 5] = v;
    }
    __syncthreads();
    if (threadIdx.x == 0) out[g] = ws[0] + ws[1] + ws[2] + ws[3] + b_pred[0];
}

// ---------------- host launcher -----------------------------------------------
extern "C" void kernel_launch(void* const* d_in, const int* in_sizes, int n_in,
                              void* d_out, int out_size) {
    const float* x       = (const float*)d_in[0];
    const int*   ei      = (const int*)d_in[1];
    const int*   batch   = (const int*)d_in[2];
    const float* W_embed = (const float*)d_in[3];
    const float* W_mpnn  = (const float*)d_in[4];
    const float* w_ih    = (const float*)d_in[5];
    const float* w_hh    = (const float*)d_in[6];
    const float* b_ih    = (const float*)d_in[7];
    const float* b_hh    = (const float*)d_in[8];
    const float* w_pred  = (const float*)d_in[9];
    const float* b_pred  = (const float*)d_in[10];
    float* out = (float*)d_out;

    int Nn = in_sizes[2];
    long long E = in_sizes[1] / 2;
    int steps = in_sizes[4] / (HID * HID);
    int F  = in_sizes[0] / Nn;      // 92
    int G = out_size;
    int KPx = F / 2;                 // 46
    int Apx = (KPx + 15) & ~15;      // 48

    cudaFuncSetAttribute(fused_step_kernel,
                         cudaFuncAttributeMaxDynamicSharedMemorySize, GIGH_SMEM);

    float *p_bcat, *p_Wfold;
    uint32_t *p_hHa, *p_hLa, *p_hHb, *p_hLb, *p_hsH, *p_hsL, *p_xH, *p_xL;
    uint32_t *p_BgTH, *p_BgTL, *p_WembTH, *p_WembTL;
    int *p_deg, *p_rowptr, *p_cursor, *p_esrc, *p_starts;
    cudaGetSymbolAddress((void**)&p_bcat,   g_bcat);
    cudaGetSymbolAddress((void**)&p_Wfold,  g_Wfold);
    cudaGetSymbolAddress((void**)&p_hHa,    g_hHa);
    cudaGetSymbolAddress((void**)&p_hLa,    g_hLa);
    cudaGetSymbolAddress((void**)&p_hHb,    g_hHb);
    cudaGetSymbolAddress((void**)&p_hLb,    g_hLb);
    cudaGetSymbolAddress((void**)&p_hsH,    g_hsH);
    cudaGetSymbolAddress((void**)&p_hsL,    g_hsL);
    cudaGetSymbolAddress((void**)&p_xH,     g_xH);
    cudaGetSymbolAddress((void**)&p_xL,     g_xL);
    cudaGetSymbolAddress((void**)&p_BgTH,   g_BgTH);
    cudaGetSymbolAddress((void**)&p_BgTL,   g_BgTL);
    cudaGetSymbolAddress((void**)&p_WembTH, g_WembTH);
    cudaGetSymbolAddress((void**)&p_WembTL, g_WembTL);
    cudaGetSymbolAddress((void**)&p_deg,    g_deg);
    cudaGetSymbolAddress((void**)&p_rowptr, g_rowptr);
    cudaGetSymbolAddress((void**)&p_cursor, g_cursor);
    cudaGetSymbolAddress((void**)&p_esrc,   g_esrc);
    cudaGetSymbolAddress((void**)&p_starts, g_starts);

    // ---- weight fold + pack ----
    {
        int tf = steps * 128 * 384;
        fold_kernel<<<(tf + 255) / 256, 256>>>(W_mpnn, w_ih, p_Wfold, steps);
        int tb = steps * 512 * 128;
        pack_BgT_kernel<<<(tb + 255) / 256, 256>>>(p_Wfold, w_hh, p_BgTH, p_BgTL, steps);
        pack_bcat_kernel<<<2, 256>>>(b_ih, b_hh, p_bcat);
        pack_wembT_kernel<<<(128 * 48 + 255) / 256, 256>>>(W_embed, p_WembTH, p_WembTL, KPx);
        long long tx = (long long)Nn * Apx;
        split_x_kernel<<<(int)((tx + 255) / 256), 256>>>(x, p_xH, p_xL, Nn, F, KPx, Apx);
    }

    // ---- CSR build + graph starts ----
    zero_i<<<(Nn + 255) / 256, 256>>>(p_deg, Nn);
    hist_kernel<<<(int)((E + 255) / 256), 256>>>(ei, E, p_deg);
    scan_kernel<<<1, 1024>>>(p_deg, p_rowptr, p_cursor, Nn);
    fill_kernel<<<(int)((E + 255) / 256), 256>>>(ei, E, p_cursor, p_esrc);
    find_starts_kernel<<<(G + 256) / 256, 256>>>(batch, Nn, G, p_starts);

    int mt = (Nn + 127) / 128;

    // ---- embed: h = tanh(x @ W_embed) -> split h (buffer A) ----
    mma_gemm_kernel<<<dim3(1, mt), 256>>>(
        p_xH, p_xL, KPx, Apx, p_WembTH, p_WembTL, 48,
        nullptr, Nn, HID, 1, p_hHa, p_hLa, 64);

    uint32_t *curH = p_hHa, *curL = p_hLa;
    uint32_t *nxtH = p_hHb, *nxtL = p_hLb;

    for (int s = 0; s < steps; s++) {
        gather_kernel<<<(int)(((long long)Nn * 32 + 255) / 256), 256>>>(
            p_rowptr, p_esrc, curH, curL, p_hsH, p_hsL, Nn);

        fused_step_kernel<<<dim3(4, mt), 256, GIGH_SMEM>>>(
            p_hsH, p_hsL, curH, curL,
            p_BgTH + (long long)s * 512 * 128, p_BgTL + (long long)s * 512 * 128,
            p_bcat, nxtH, nxtL, Nn);

        uint32_t* t;
        t = curH; curH = nxtH; nxtH = t;
        t = curL; curL = nxtL; nxtL = t;
    }

    pool_final_kernel<<<G, 512>>>(curH, curL, p_starts, w_pred, b_pred, out);
}

// round 17
// speedup vs baseline: 1.5216x; 1.0382x over previous
#include <cuda_runtime.h>
#include <cuda_bf16.h>
#include <math.h>
#include <stdint.h>

#define HID 128
#define MAX_N 100352
#define MAXSTEPS 8
#define NG 256
#define MAX_E 2000000

// ---------------- scratch (static device globals; no runtime allocation) ----
// interleaved split storage: row n, pair p -> word n*P*2 + p*2 (+0=H, +1=L)
__device__ __align__(16) uint32_t g_hIa [MAX_N * 128];     // ping-pong h
__device__ __align__(16) uint32_t g_hIb [MAX_N * 128];
__device__ __align__(16) uint32_t g_hsI [MAX_N * 128];     // hsum
__device__ __align__(16) uint32_t g_xI  [MAX_N * 96];      // x (48 pairs padded)
__device__ __align__(16) float    g_Wfold[MAXSTEPS * 128 * 384];   // W_mpnn[s] @ w_ih^T
__device__ __align__(16) uint32_t g_BgTH[MAXSTEPS * 512 * 128];    // permuted B'' split
__device__ __align__(16) uint32_t g_BgTL[MAXSTEPS * 512 * 128];
__device__ __align__(16) uint32_t g_WembTH[128 * 48];
__device__ __align__(16) uint32_t g_WembTL[128 * 48];
__device__ __align__(16) float    g_bcat[512];             // permuted bias
__device__ int g_deg[MAX_N];
__device__ int g_rowptr[MAX_N + 1];
__device__ int g_cursor[MAX_N];
__device__ int g_esrc[MAX_E];
__device__ int g_starts[NG + 1];

// ---------------- helpers ----------------------------------------------------
__device__ __forceinline__ void split2(float x, float y, uint32_t& hi, uint32_t& lo) {
    __nv_bfloat16 hx = __float2bfloat16_rn(x);
    __nv_bfloat16 hy = __float2bfloat16_rn(y);
    float rx = x - __bfloat162float(hx);
    float ry = y - __bfloat162float(hy);
    __nv_bfloat162 h; h.x = hx; h.y = hy;
    __nv_bfloat162 l; l.x = __float2bfloat16_rn(rx); l.y = __float2bfloat16_rn(ry);
    hi = *(uint32_t*)&h;
    lo = *(uint32_t*)&l;
}

__device__ __forceinline__ void unsplit2(uint32_t hi, uint32_t lo, float& x, float& y) {
    __nv_bfloat162 h = *(__nv_bfloat162*)&hi;
    __nv_bfloat162 l = *(__nv_bfloat162*)&lo;
    x = __bfloat162float(h.x) + __bfloat162float(l.x);
    y = __bfloat162float(h.y) + __bfloat162float(l.y);
}

__device__ __forceinline__ void mma_bf16(float* c, const uint32_t* a, const uint32_t* b) {
    asm volatile(
        "mma.sync.aligned.m16n8k16.row.col.f32.bf16.bf16.f32 "
        "{%0,%1,%2,%3}, {%4,%5,%6,%7}, {%8,%9}, {%0,%1,%2,%3};\n"
        : "+f"(c[0]), "+f"(c[1]), "+f"(c[2]), "+f"(c[3])
        : "r"(a[0]), "r"(a[1]), "r"(a[2]), "r"(a[3]),
          "r"(b[0]), "r"(b[1]));
}

__device__ __forceinline__ void ldsm4(uint32_t& r0, uint32_t& r1,
                                      uint32_t& r2, uint32_t& r3, uint32_t addr) {
    asm volatile("ldmatrix.sync.aligned.m8n8.x4.shared.b16 {%0,%1,%2,%3}, [%4];"
                 : "=r"(r0), "=r"(r1), "=r"(r2), "=r"(r3) : "r"(addr));
}

__device__ __forceinline__ float sigmoidf_(float x) {
    return 1.0f / (1.0f + expf(-x));
}

// ---------------- small utility kernels --------------------------------------
__global__ void zero_i(int* p, int n) {
    int i = blockIdx.x * blockDim.x + threadIdx.x;
    if (i < n) p[i] = 0;
}

// ---------------- weight fold / pack kernels ----------------------------------
// Wfold[s] = W_mpnn[s] @ w_ih^T   : [128 K][384 cols]
__global__ void fold_kernel(const float* __restrict__ Wm,
                            const float* __restrict__ wih,
                            float* __restrict__ Wfold, int steps) {
    int idx = blockIdx.x * blockDim.x + threadIdx.x;
    int total = steps * 128 * 384;
    if (idx >= total) return;
    int s = idx / (128 * 384);
    int rem = idx % (128 * 384);
    int k = rem / 384;
    int j = rem % 384;
    const float* wr = Wm + s * 128 * 128 + k * 128;
    const float* ir = wih + j * 128;
    float acc = 0.0f;
#pragma unroll 8
    for (int c = 0; c < 128; c++) acc = fmaf(wr[c], ir[c], acc);
    Wfold[idx] = acc;
}

// permuted B'': reordered col C in [0,512): comp=(C>>3)&3,
// hidx = (C>>7)*32 + ((C>>5)&3)*8 + (C&7). K=[hsum kpairs 0..63 | h kpairs 64..127].
// comp0=r_sum, comp1=z_sum, comp2=i_n (hsum half only), comp3=h_n (h half only).
__global__ void pack_BgT_kernel(const float* __restrict__ Wfold,
                                const float* __restrict__ whh,
                                uint32_t* __restrict__ WH, uint32_t* __restrict__ WL,
                                int steps) {
    int idx = blockIdx.x * blockDim.x + threadIdx.x;
    int total = steps * 512 * 128;
    if (idx >= total) return;
    int s = idx / (512 * 128);
    int rem = idx % (512 * 128);
    int C = rem / 128;
    int p = rem % 128;
    int comp = (C >> 3) & 3;
    int hidx = (C >> 7) * 32 + ((C >> 5) & 3) * 8 + (C & 7);
    float a = 0.f, b = 0.f;
    if (p < 64) {                      // hsum half: Wfold cols (comp<3)
        int k0 = 2 * p;
        if (comp < 3) {
            int j = comp * 128 + hidx;
            a = Wfold[s * 128 * 384 + k0 * 384 + j];
            b = Wfold[s * 128 * 384 + (k0 + 1) * 384 + j];
        }
    } else {                           // h half: w_hh rows
        int k0 = 2 * (p - 64);
        int jj = -1;
        if (comp == 0)      jj = hidx;
        else if (comp == 1) jj = 128 + hidx;
        else if (comp == 3) jj = 256 + hidx;
        if (jj >= 0) { a = whh[jj * HID + k0]; b = whh[jj * HID + k0 + 1]; }
    }
    uint32_t h, l;
    split2(a, b, h, l);
    WH[idx] = h; WL[idx] = l;
}

__global__ void pack_bcat_kernel(const float* __restrict__ bih,
                                 const float* __restrict__ bhh,
                                 float* __restrict__ bcat) {
    int C = blockIdx.x * blockDim.x + threadIdx.x;
    if (C >= 512) return;
    int comp = (C >> 3) & 3;
    int hidx = (C >> 7) * 32 + ((C >> 5) & 3) * 8 + (C & 7);
    float v;
    if (comp == 0)      v = bih[hidx] + bhh[hidx];
    else if (comp == 1) v = bih[128 + hidx] + bhh[128 + hidx];
    else if (comp == 2) v = bih[256 + hidx];
    else                v = bhh[256 + hidx];
    bcat[C] = v;
}

__global__ void pack_wembT_kernel(const float* __restrict__ We,
                                  uint32_t* __restrict__ WH, uint32_t* __restrict__ WL,
                                  int KPx) {
    int idx = blockIdx.x * blockDim.x + threadIdx.x;
    if (idx >= 128 * 48) return;
    int j = idx / 48;
    int p = idx % 48;
    uint32_t h = 0, l = 0;
    if (p < KPx) split2(We[(2 * p) * HID + j], We[(2 * p + 1) * HID + j], h, l);
    WH[idx] = h; WL[idx] = l;
}

// xI: interleaved [N][48 pairs][2]
__global__ void split_x_kernel(const float* __restrict__ x,
                               uint32_t* __restrict__ xI,
                               int Nn, int F, int KPx, int Apx) {
    long long idx = (long long)blockIdx.x * blockDim.x + threadIdx.x;
    if (idx >= (long long)Nn * Apx) return;
    int n = (int)(idx / Apx);
    int p = (int)(idx % Apx);
    uint32_t h = 0, l = 0;
    if (p < KPx) split2(x[(long long)n * F + 2 * p], x[(long long)n * F + 2 * p + 1], h, l);
    long long w = (long long)n * (Apx * 2) + p * 2;
    xI[w] = h; xI[w + 1] = l;
}

// ---------------- CSR build ---------------------------------------------------
__global__ void hist_kernel(const int* __restrict__ ei, long long E, int* __restrict__ deg) {
    long long e = (long long)blockIdx.x * blockDim.x + threadIdx.x;
    if (e >= E) return;
    atomicAdd(&deg[ei[E + e]], 1);
}

__global__ void scan_kernel(const int* __restrict__ deg, int* __restrict__ rowptr,
                            int* __restrict__ cursor, int Nn) {
    __shared__ int warpsums[32];
    const int tid = threadIdx.x;
    const int lane = tid & 31;
    const int wid = tid >> 5;
    int carry = 0;
    for (int base = 0; base < Nn; base += 1024) {
        int idx = base + tid;
        int v = (idx < Nn) ? deg[idx] : 0;
        int x = v;
#pragma unroll
        for (int off = 1; off < 32; off <<= 1) {
            int y = __shfl_up_sync(0xffffffffu, x, off);
            if (lane >= off) x += y;
        }
        if (lane == 31) warpsums[wid] = x;
        __syncthreads();
        if (wid == 0) {
            int z = warpsums[lane];
#pragma unroll
            for (int off = 1; off < 32; off <<= 1) {
                int y = __shfl_up_sync(0xffffffffu, z, off);
                if (lane >= off) z += y;
            }
            warpsums[lane] = z;
        }
        __syncthreads();
        int pref = (wid > 0) ? warpsums[wid - 1] : 0;
        int excl = carry + pref + x - v;
        if (idx < Nn) { rowptr[idx] = excl; cursor[idx] = excl; }
        carry += warpsums[31];
        __syncthreads();
    }
    if (tid == 0) rowptr[Nn] = carry;
}

__global__ void fill_kernel(const int* __restrict__ ei, long long E,
                            int* __restrict__ cursor, int* __restrict__ esrc) {
    long long e = (long long)blockIdx.x * blockDim.x + threadIdx.x;
    if (e >= E) return;
    int s = ei[e];
    int d = ei[E + e];
    int p = atomicAdd(&cursor[d], 1);
    esrc[p] = s;
}

// ---------------- generic bf16-split GEMM with ldmatrix (embed only) ----------
// A interleaved: AI [M][Apitch pairs][2]. B split BTH/BTL [N][Bpitch pairs].
__global__ __launch_bounds__(256)
void mma_gemm_kernel(const uint32_t* __restrict__ AI,
                     int KP, int Apitch,
                     const uint32_t* __restrict__ BTH, const uint32_t* __restrict__ BTL,
                     int Bpitch,
                     float* __restrict__ C, int M, int N, int act,
                     uint32_t* __restrict__ outI, int opitch) {
    __shared__ uint32_t AsH[128 * 20];
    __shared__ uint32_t AsL[128 * 20];
    __shared__ uint32_t BsH[128 * 20];
    __shared__ uint32_t BsL[128 * 20];

    const int tid  = threadIdx.x;
    const int lane = tid & 31;
    const int warp = tid >> 5;
    const int warpM = warp >> 2;
    const int warpN = warp & 3;
    const int row0 = blockIdx.y * 128;
    const int col0 = blockIdx.x * 128;

    const uint32_t aHb = (uint32_t)__cvta_generic_to_shared(AsH);
    const uint32_t aLb = (uint32_t)__cvta_generic_to_shared(AsL);
    const uint32_t bHb = (uint32_t)__cvta_generic_to_shared(BsH);
    const uint32_t bLb = (uint32_t)__cvta_generic_to_shared(BsL);

    const int lr   = tid >> 2;
    const int lkp4 = (tid & 3) * 4;
    const int a_lane_off = (lane & 15) * 20 + ((lane >> 4) << 2);
    const int b_lane_off = ((lane & 7) + ((lane >> 4) << 3)) * 20 + (((lane >> 3) & 1) << 2);

    float acc[4][4][4];
#pragma unroll
    for (int mi = 0; mi < 4; mi++)
#pragma unroll
        for (int ni = 0; ni < 4; ni++)
#pragma unroll
            for (int q = 0; q < 4; q++) acc[mi][ni][q] = 0.0f;

    const int ntiles = (KP + 15) >> 4;

    for (int t = 0; t < ntiles; t++) {
        const int ktp = t * 16;
#pragma unroll
        for (int i = 0; i < 2; i++) {
            int r  = lr + i * 64;
            int gr = row0 + r;
            uint4 q0 = make_uint4(0, 0, 0, 0);
            uint4 q1 = make_uint4(0, 0, 0, 0);
            if (gr < M) {
                long long off = (long long)gr * (Apitch * 2) + (ktp + lkp4) * 2;
                q0 = *(const uint4*)&AI[off];
                q1 = *(const uint4*)&AI[off + 4];
            }
            *(uint4*)&AsH[r * 20 + lkp4] = make_uint4(q0.x, q0.z, q1.x, q1.z);
            *(uint4*)&AsL[r * 20 + lkp4] = make_uint4(q0.y, q0.w, q1.y, q1.w);
        }
#pragma unroll
        for (int i = 0; i < 2; i++) {
            int r = lr + i * 64;
            long long off = (long long)(col0 + r) * Bpitch + ktp + lkp4;
            *(uint4*)&BsH[r * 20 + lkp4] = *(const uint4*)&BTH[off];
            *(uint4*)&BsL[r * 20 + lkp4] = *(const uint4*)&BTL[off];
        }
        __syncthreads();

#pragma unroll
        for (int ks = 0; ks < 2; ks++) {
            const int kp0 = ks * 8;
            uint32_t bfh[4][2], bfl[4][2];
#pragma unroll
            for (int ni2 = 0; ni2 < 2; ni2++) {
                uint32_t off = (uint32_t)(((warpN * 32 + ni2 * 16) * 20 + kp0 + b_lane_off) * 4);
                ldsm4(bfh[ni2 * 2][0], bfh[ni2 * 2][1],
                      bfh[ni2 * 2 + 1][0], bfh[ni2 * 2 + 1][1], bHb + off);
                ldsm4(bfl[ni2 * 2][0], bfl[ni2 * 2][1],
                      bfl[ni2 * 2 + 1][0], bfl[ni2 * 2 + 1][1], bLb + off);
            }
#pragma unroll
            for (int mi = 0; mi < 4; mi++) {
                uint32_t off = (uint32_t)(((warpM * 64 + mi * 16) * 20 + kp0 + a_lane_off) * 4);
                uint32_t afh[4], afl[4];
                ldsm4(afh[0], afh[1], afh[2], afh[3], aHb + off);
                ldsm4(afl[0], afl[1], afl[2], afl[3], aLb + off);
#pragma unroll
                for (int ni = 0; ni < 4; ni++) {
                    mma_bf16(acc[mi][ni], afh, bfl[ni]);
                    mma_bf16(acc[mi][ni], afl, bfh[ni]);
                    mma_bf16(acc[mi][ni], afh, bfh[ni]);
                }
            }
        }
        __syncthreads();
    }

#pragma unroll
    for (int mi = 0; mi < 4; mi++) {
#pragma unroll
        for (int ni = 0; ni < 4; ni++) {
            int c = col0 + warpN * 32 + ni * 8 + (lane & 3) * 2;
#pragma unroll
            for (int half = 0; half < 2; half++) {
                int r = row0 + warpM * 64 + mi * 16 + (lane >> 2) + half * 8;
                if (r >= M) continue;
                float v0 = acc[mi][ni][half * 2 + 0];
                float v1 = acc[mi][ni][half * 2 + 1];
                if (act == 1) { v0 = tanhf(v0); v1 = tanhf(v1); }
                if (C != nullptr)
                    *(float2*)(C + (long long)r * N + c) = make_float2(v0, v1);
                if (outI != nullptr) {
                    uint32_t hh, ll;
                    split2(v0, v1, hh, ll);
                    long long w = (long long)r * (opitch * 2) + (c >> 1) * 2;
                    *(uint2*)&outI[w] = make_uint2(hh, ll);
                }
            }
        }
    }
}

// ---------------- fused step GEMM + GRU gate (R14 config, interleaved I/O) ----
// B-half resident in smem (64 kpairs, pitch 68); A tiled 16 kpairs (pitch 20).
#define GIGH_SMEM ((2 * 128 * 68 + 2 * 128 * 20) * 4)

__global__ __launch_bounds__(256)
void fused_step_kernel(const uint32_t* __restrict__ hsI,
                       const uint32_t* __restrict__ hI,
                       const uint32_t* __restrict__ BTH, const uint32_t* __restrict__ BTL,
                       const float* __restrict__ bcat,
                       uint32_t* __restrict__ hIn,
                       int M) {
    extern __shared__ uint32_t smem[];
    uint32_t* BsH = smem;                        // [128][68]
    uint32_t* BsL = smem + 128 * 68;
    uint32_t* AsH = smem + 2 * 128 * 68;         // [128][20]
    uint32_t* AsL = smem + 2 * 128 * 68 + 128 * 20;

    const int tid  = threadIdx.x;
    const int lane = tid & 31;
    const int warp = tid >> 5;
    const int warpM = warp >> 2;
    const int warpN = warp & 3;
    const int row0 = blockIdx.y * 128;
    const int col0 = blockIdx.x * 128;

    const uint32_t aHb = (uint32_t)__cvta_generic_to_shared(AsH);
    const uint32_t aLb = (uint32_t)__cvta_generic_to_shared(AsL);
    const uint32_t bHb = (uint32_t)__cvta_generic_to_shared(BsH);
    const uint32_t bLb = (uint32_t)__cvta_generic_to_shared(BsL);

    const int lr   = tid >> 2;
    const int lkp4 = (tid & 3) * 4;
    const int a_lane_off = (lane & 15) * 20 + ((lane >> 4) << 2);
    const int b_lane_off = ((lane & 7) + ((lane >> 4) << 3)) * 68 + (((lane >> 3) & 1) << 2);

    float acc[4][4][4];
#pragma unroll
    for (int mi = 0; mi < 4; mi++)
#pragma unroll
        for (int ni = 0; ni < 4; ni++)
#pragma unroll
            for (int q = 0; q < 4; q++) acc[mi][ni][q] = 0.0f;

    // ---- two phases: bhalf 0 (A=hsum, ni 0,1,2) and bhalf 1 (A=h, ni 0,1,3)
#pragma unroll
    for (int bhalf = 0; bhalf < 2; bhalf++) {
        // load resident B half: 128 cols x 64 kpairs
#pragma unroll
        for (int i = 0; i < 2; i++) {
            int col = lr + i * 64;
#pragma unroll
            for (int kk = 0; kk < 4; kk++) {
                int kp = lkp4 + kk * 16;
                long long off = (long long)(col0 + col) * 128 + bhalf * 64 + kp;
                *(uint4*)&BsH[col * 68 + kp] = *(const uint4*)&BTH[off];
                *(uint4*)&BsL[col * 68 + kp] = *(const uint4*)&BTL[off];
            }
        }
        const uint32_t* srcI = bhalf ? hI : hsI;

        for (int tt = 0; tt < 4; tt++) {
            const int ktp_loc = tt * 16;
#pragma unroll
            for (int i = 0; i < 2; i++) {
                int r  = lr + i * 64;
                int gr = row0 + r;
                uint4 q0 = make_uint4(0, 0, 0, 0);
                uint4 q1 = make_uint4(0, 0, 0, 0);
                if (gr < M) {
                    long long off = (long long)gr * 128 + (ktp_loc + lkp4) * 2;
                    q0 = *(const uint4*)&srcI[off];
                    q1 = *(const uint4*)&srcI[off + 4];
                }
                *(uint4*)&AsH[r * 20 + lkp4] = make_uint4(q0.x, q0.z, q1.x, q1.z);
                *(uint4*)&AsL[r * 20 + lkp4] = make_uint4(q0.y, q0.w, q1.y, q1.w);
            }
            __syncthreads();

#pragma unroll
            for (int ks = 0; ks < 2; ks++) {
                const int kp0 = ks * 8;
                const int kpb = tt * 16 + kp0;
                uint32_t bfh[4][2], bfl[4][2];
#pragma unroll
                for (int ni2 = 0; ni2 < 2; ni2++) {
                    uint32_t off = (uint32_t)(((warpN * 32 + ni2 * 16) * 68 + kpb + b_lane_off) * 4);
                    ldsm4(bfh[ni2 * 2][0], bfh[ni2 * 2][1],
                          bfh[ni2 * 2 + 1][0], bfh[ni2 * 2 + 1][1], bHb + off);
                    ldsm4(bfl[ni2 * 2][0], bfl[ni2 * 2][1],
                          bfl[ni2 * 2 + 1][0], bfl[ni2 * 2 + 1][1], bLb + off);
                }
#pragma unroll
                for (int mi = 0; mi < 4; mi++) {
                    uint32_t off = (uint32_t)(((warpM * 64 + mi * 16) * 20 + kp0 + a_lane_off) * 4);
                    uint32_t afh[4], afl[4];
                    ldsm4(afh[0], afh[1], afh[2], afh[3], aHb + off);
                    ldsm4(afl[0], afl[1], afl[2], afl[3], aLb + off);
#pragma unroll
                    for (int ni = 0; ni < 4; ni++) {
                        // skip structurally-zero blocks: h_n on hsum half, i_n on h half
                        if (bhalf == 0 && ni == 3) continue;
                        if (bhalf == 1 && ni == 2) continue;
                        mma_bf16(acc[mi][ni], afh, bfl[ni]);
                        mma_bf16(acc[mi][ni], afl, bfh[ni]);
                        mma_bf16(acc[mi][ni], afh, bfh[ni]);
                    }
                }
            }
            __syncthreads();
        }
    }

    // ---- fused GRU epilogue ----
    const int c2 = (lane & 3) * 2;
    const int hidx0 = blockIdx.x * 32 + warpN * 8 + c2;
    const int u = hidx0 >> 1;     // pair index within h row
    float bc[4][2];
#pragma unroll
    for (int ni = 0; ni < 4; ni++) {
        int C = col0 + warpN * 32 + ni * 8 + c2;
        bc[ni][0] = bcat[C];
        bc[ni][1] = bcat[C + 1];
    }

#pragma unroll
    for (int mi = 0; mi < 4; mi++) {
#pragma unroll
        for (int half = 0; half < 2; half++) {
            int r = row0 + warpM * 64 + mi * 16 + (lane >> 2) + half * 8;
            if (r >= M) continue;
            long long w = (long long)r * 128 + u * 2;
            uint2 ho = *(const uint2*)&hI[w];
            float ho0, ho1;
            unsplit2(ho.x, ho.y, ho0, ho1);
            float hn0, hn1;
            {
                float rp = acc[mi][0][half * 2 + 0] + bc[0][0];
                float zp = acc[mi][1][half * 2 + 0] + bc[1][0];
                float ip = acc[mi][2][half * 2 + 0] + bc[2][0];
                float hp = acc[mi][3][half * 2 + 0] + bc[3][0];
                float rr = sigmoidf_(rp), zz = sigmoidf_(zp);
                float cand = tanhf(ip + rr * hp);
                hn0 = (1.0f - zz) * cand + zz * ho0;
            }
            {
                float rp = acc[mi][0][half * 2 + 1] + bc[0][1];
                float zp = acc[mi][1][half * 2 + 1] + bc[1][1];
                float ip = acc[mi][2][half * 2 + 1] + bc[2][1];
                float hp = acc[mi][3][half * 2 + 1] + bc[3][1];
                float rr = sigmoidf_(rp), zz = sigmoidf_(zp);
                float cand = tanhf(ip + rr * hp);
                hn1 = (1.0f - zz) * cand + zz * ho1;
            }
            uint32_t hh, ll;
            split2(hn0, hn1, hh, ll);
            *(uint2*)&hIn[w] = make_uint2(hh, ll);
        }
    }
}

// ---------------- CSR gather-reduce (interleaved, 2-edge unrolled) ------------
__global__ void gather_kernel(const int* __restrict__ rowptr,
                              const int* __restrict__ esrc,
                              const uint32_t* __restrict__ hI,
                              uint32_t* __restrict__ hsI,
                              int Nn) {
    int w = (int)(((long long)blockIdx.x * blockDim.x + threadIdx.x) >> 5);
    int lane = threadIdx.x & 31;
    if (w >= Nn) return;
    int i = rowptr[w];
    const int end = rowptr[w + 1];
    const int w4 = lane * 4;           // word offset: pairs 2*lane, 2*lane+1
    float a0 = 0.f, a1 = 0.f, a2 = 0.f, a3 = 0.f;
    for (; i + 1 < end; i += 2) {
        int sa = esrc[i];
        int sb = esrc[i + 1];
        uint4 va = *(const uint4*)&hI[(long long)sa * 128 + w4];
        uint4 vb = *(const uint4*)&hI[(long long)sb * 128 + w4];
        float x0, y0, x1, y1;
        unsplit2(va.x, va.y, x0, y0);
        unsplit2(va.z, va.w, x1, y1);
        a0 += x0; a1 += y0; a2 += x1; a3 += y1;
        unsplit2(vb.x, vb.y, x0, y0);
        unsplit2(vb.z, vb.w, x1, y1);
        a0 += x0; a1 += y0; a2 += x1; a3 += y1;
    }
    if (i < end) {
        int s = esrc[i];
        uint4 v = *(const uint4*)&hI[(long long)s * 128 + w4];
        float x0, y0, x1, y1;
        unsplit2(v.x, v.y, x0, y0);
        unsplit2(v.z, v.w, x1, y1);
        a0 += x0; a1 += y0; a2 += x1; a3 += y1;
    }
    uint32_t h0, l0, h1, l1;
    split2(a0, a1, h0, l0);
    split2(a2, a3, h1, l1);
    *(uint4*)&hsI[(long long)w * 128 + w4] = make_uint4(h0, l0, h1, l1);
}

// ---------------- sorted-batch pooling + head ---------------------------------
__global__ void find_starts_kernel(const int* __restrict__ batch, int Nn, int G,
                                   int* __restrict__ starts) {
    int g = blockIdx.x * blockDim.x + threadIdx.x;
    if (g > G) return;
    if (g == G) { starts[G] = Nn; return; }
    int lo = 0, hi = Nn;
    while (lo < hi) {
        int mid = (lo + hi) >> 1;
        if (batch[mid] < g) lo = mid + 1; else hi = mid;
    }
    starts[g] = lo;
}

// 512 threads: 4 node-striped subsets of 128 feature-lanes, then smem reduce.
__global__ void pool_final_kernel(const uint32_t* __restrict__ hI,
                                  const int* __restrict__ starts,
                                  const float* __restrict__ w_pred,
                                  const float* __restrict__ b_pred,
                                  float* __restrict__ out) {
    __shared__ float part[4][128];
    __shared__ float ws[4];
    int g = blockIdx.x;
    int t = threadIdx.x & 127;     // feature index
    int sub = threadIdx.x >> 7;    // 0..3
    int s = starts[g], e = starts[g + 1];
    int u = t >> 1;
    int half = t & 1;
    float acc = 0.0f;
    for (int n = s + sub; n < e; n += 4) {
        uint2 v = *(const uint2*)&hI[(long long)n * 128 + u * 2];
        float a, bq;
        unsplit2(v.x, v.y, a, bq);
        acc += half ? bq : a;
    }
    part[sub][t] = acc;
    __syncthreads();
    if (threadIdx.x < 128) {
        float total = part[0][t] + part[1][t] + part[2][t] + part[3][t];
        float c = fmaxf((float)(e - s), 1.0f);
        float v = fmaxf(total / c, 0.0f) * w_pred[t];
#pragma unroll
        for (int o = 16; o > 0; o >>= 1) v += __shfl_down_sync(0xffffffffu, v, o);
        if ((t & 31) == 0) ws[t >> 5] = v;
    }
    __syncthreads();
    if (threadIdx.x == 0) out[g] = ws[0] + ws[1] + ws[2] + ws[3] + b_pred[0];
}

// ---------------- host launcher -----------------------------------------------
extern "C" void kernel_launch(void* const* d_in, const int* in_sizes, int n_in,
                              void* d_out, int out_size) {
    const float* x       = (const float*)d_in[0];
    const int*   ei      = (const int*)d_in[1];
    const int*   batch   = (const int*)d_in[2];
    const float* W_embed = (const float*)d_in[3];
    const float* W_mpnn  = (const float*)d_in[4];
    const float* w_ih    = (const float*)d_in[5];
    const float* w_hh    = (const float*)d_in[6];
    const float* b_ih    = (const float*)d_in[7];
    const float* b_hh    = (const float*)d_in[8];
    const float* w_pred  = (const float*)d_in[9];
    const float* b_pred  = (const float*)d_in[10];
    float* out = (float*)d_out;

    int Nn = in_sizes[2];
    long long E = in_sizes[1] / 2;
    int steps = in_sizes[4] / (HID * HID);
    int F  = in_sizes[0] / Nn;      // 92
    int G = out_size;
    int KPx = F / 2;                 // 46
    int Apx = (KPx + 15) & ~15;      // 48

    cudaFuncSetAttribute(fused_step_kernel,
                         cudaFuncAttributeMaxDynamicSharedMemorySize, GIGH_SMEM);

    float *p_bcat, *p_Wfold;
    uint32_t *p_hIa, *p_hIb, *p_hsI, *p_xI;
    uint32_t *p_BgTH, *p_BgTL, *p_WembTH, *p_WembTL;
    int *p_deg, *p_rowptr, *p_cursor, *p_esrc, *p_starts;
    cudaGetSymbolAddress((void**)&p_bcat,   g_bcat);
    cudaGetSymbolAddress((void**)&p_Wfold,  g_Wfold);
    cudaGetSymbolAddress((void**)&p_hIa,    g_hIa);
    cudaGetSymbolAddress((void**)&p_hIb,    g_hIb);
    cudaGetSymbolAddress((void**)&p_hsI,    g_hsI);
    cudaGetSymbolAddress((void**)&p_xI,     g_xI);
    cudaGetSymbolAddress((void**)&p_BgTH,   g_BgTH);
    cudaGetSymbolAddress((void**)&p_BgTL,   g_BgTL);
    cudaGetSymbolAddress((void**)&p_WembTH, g_WembTH);
    cudaGetSymbolAddress((void**)&p_WembTL, g_WembTL);
    cudaGetSymbolAddress((void**)&p_deg,    g_deg);
    cudaGetSymbolAddress((void**)&p_rowptr, g_rowptr);
    cudaGetSymbolAddress((void**)&p_cursor, g_cursor);
    cudaGetSymbolAddress((void**)&p_esrc,   g_esrc);
    cudaGetSymbolAddress((void**)&p_starts, g_starts);

    // ---- weight fold + pack ----
    {
        int tf = steps * 128 * 384;
        fold_kernel<<<(tf + 255) / 256, 256>>>(W_mpnn, w_ih, p_Wfold, steps);
        int tb = steps * 512 * 128;
        pack_BgT_kernel<<<(tb + 255) / 256, 256>>>(p_Wfold, w_hh, p_BgTH, p_BgTL, steps);
        pack_bcat_kernel<<<2, 256>>>(b_ih, b_hh, p_bcat);
        pack_wembT_kernel<<<(128 * 48 + 255) / 256, 256>>>(W_embed, p_WembTH, p_WembTL, KPx);
        long long tx = (long long)Nn * Apx;
        split_x_kernel<<<(int)((tx + 255) / 256), 256>>>(x, p_xI, Nn, F, KPx, Apx);
    }

    // ---- CSR build + graph starts ----
    zero_i<<<(Nn + 255) / 256, 256>>>(p_deg, Nn);
    hist_kernel<<<(int)((E + 255) / 256), 256>>>(ei, E, p_deg);
    scan_kernel<<<1, 1024>>>(p_deg, p_rowptr, p_cursor, Nn);
    fill_kernel<<<(int)((E + 255) / 256), 256>>>(ei, E, p_cursor, p_esrc);
    find_starts_kernel<<<(G + 256) / 256, 256>>>(batch, Nn, G, p_starts);

    int mt = (Nn + 127) / 128;

    // ---- embed: h = tanh(x @ W_embed) -> interleaved split h (buffer A) ----
    mma_gemm_kernel<<<dim3(1, mt), 256>>>(
        p_xI, KPx, Apx, p_WembTH, p_WembTL, 48,
        nullptr, Nn, HID, 1, p_hIa, 64);

    uint32_t *curI = p_hIa;
    uint32_t *nxtI = p_hIb;

    for (int s = 0; s < steps; s++) {
        gather_kernel<<<(int)(((long long)Nn * 32 + 255) / 256), 256>>>(
            p_rowptr, p_esrc, curI, p_hsI, Nn);

        fused_step_kernel<<<dim3(4, mt), 256, GIGH_SMEM>>>(
            p_hsI, curI,
            p_BgTH + (long long)s * 512 * 128, p_BgTL + (long long)s * 512 * 128,
            p_bcat, nxtI, Nn);

        uint32_t* t = curI; curI = nxtI; nxtI = t;
    }

    pool_final_kernel<<<G, 512>>>(curI, p_starts, w_pred, b_pred, out);
}